// round 10
// baseline (speedup 1.0000x reference)
#include <cuda_runtime.h>
#include <cstdint>

#define MAXB 2048
#define ISTR 260      // smem batch stride (floats); 1040B = 16B-aligned
#define NB 16         // batches per CTA (k1/k3)
#define CTXH (NB*ISTR)

__device__ float g_qW[MAXB * 1024];   // (q_h @ W_k,h)/TEMP  [b][h][j]
__device__ float g_ctx[MAXB * 1024];  // attn @ seq          [b][h][j]
// transposed weights: Wt[k][c], c contiguous (256 cols)
__device__ float g_wqs_t[256*256];
__device__ float g_wvs_t[256*256];
__device__ float g_fcw_t[256*256];
__device__ float g_fc2_t[256*256];
__device__ float g_fc1_t[512*256];

extern __shared__ float s_dyn[];

// ---------------- f32x2 / cp.async helpers ----------------
__device__ __forceinline__ uint64_t pk(float x, float y){
    uint64_t r; asm("mov.b64 %0, {%1,%2};" : "=l"(r) : "f"(x), "f"(y)); return r;
}
__device__ __forceinline__ float lo32(uint64_t v){ return __uint_as_float((unsigned)(v & 0xffffffffu)); }
__device__ __forceinline__ float hi32(uint64_t v){ return __uint_as_float((unsigned)(v >> 32)); }
__device__ __forceinline__ void fma2(uint64_t& d, uint64_t a, uint64_t b){
    asm("fma.rn.f32x2 %0, %1, %2, %0;" : "+l"(d) : "l"(a), "l"(b));
}
__device__ __forceinline__ void mul2(uint64_t& d, uint64_t r){
    asm("mul.rn.f32x2 %0, %1, %2;" : "=l"(d) : "l"(d), "l"(r));
}
__device__ __forceinline__ void ldsv2(uint64_t& a, uint64_t& b, const float* p){
    uint32_t sp = (uint32_t)__cvta_generic_to_shared(p);
    asm volatile("ld.shared.v2.u64 {%0,%1}, [%2];" : "=l"(a), "=l"(b) : "r"(sp));
}
__device__ __forceinline__ void cp16(float* dst, const float* src){
    uint32_t s = (uint32_t)__cvta_generic_to_shared(dst);
    asm volatile("cp.async.cg.shared.global [%0], [%1], 16;" :: "r"(s), "l"(src));
}
#define CP_COMMIT() asm volatile("cp.async.commit_group;" ::: "memory")
#define CP_WAIT(N)  asm volatile("cp.async.wait_group %0;" :: "n"(N) : "memory")

// ---------------------------------------------------------------------------
// Weight transpose: Wt[k][c] = W[c][k].  32x32 smem tiles. 5 weights, 1 launch.
// ---------------------------------------------------------------------------
__global__ void __launch_bounds__(256) tr_all(const float* __restrict__ w_qs,
                                              const float* __restrict__ w_vs,
                                              const float* __restrict__ fc_w,
                                              const float* __restrict__ fc1_w,
                                              const float* __restrict__ fc2_w)
{
    __shared__ float ts[32][33];
    int id = blockIdx.x;
    const float* src; float* dst; int K, tile;
    if      (id < 64) { src = w_qs;  dst = g_wqs_t; K = 256; tile = id; }
    else if (id < 128){ src = w_vs;  dst = g_wvs_t; K = 256; tile = id - 64; }
    else if (id < 192){ src = fc_w;  dst = g_fcw_t; K = 256; tile = id - 128; }
    else if (id < 320){ src = fc1_w; dst = g_fc1_t; K = 512; tile = id - 192; }
    else              { src = fc2_w; dst = g_fc2_t; K = 256; tile = id - 320; }
    int ntk = K >> 5;
    int tc = tile / ntk, tk = tile % ntk;
    int c0 = tc*32, k0 = tk*32;
    int tx = threadIdx.x & 31, ty = threadIdx.x >> 5;
    #pragma unroll
    for (int r = 0; r < 32; r += 8)
        ts[ty + r][tx] = src[(size_t)(c0 + ty + r)*K + k0 + tx];
    __syncthreads();
    #pragma unroll
    for (int r = 0; r < 32; r += 8)
        dst[(size_t)(k0 + ty + r)*256 + c0 + tx] = ts[tx][ty + r];
}

// ---------------------------------------------------------------------------
// Direct-LDG GEMV core ("head-stage pattern"):
//   out[b, c] += sum_k in[b, k] * Wt[k][c]     (Wt c-contiguous, row 256 floats)
// Thread map: hcg = t&63 (col quad c = hcg*4..+3), hbg = t>>6 (batches i*4+hbg).
// Per k: 1 coalesced LDG.128 (native f32x2 col pairs), NI broadcast LDS + pack,
// 2*NI FMA2. No barriers, no smem weight staging. Weights L2/L1-resident.
// ---------------------------------------------------------------------------
template<int NI, int K>
__device__ __forceinline__ void dgemv(const float4* __restrict__ wp,   // &Wt[0][hcg*4]
                                      const float* __restrict__ inb,   // in_s + hbg*ISTR (+k offset)
                                      uint64_t (&a01)[NI], uint64_t (&a23)[NI])
{
    #pragma unroll 8
    for (int k = 0; k < K; k++){
        float4 w = __ldg(wp + (size_t)k*64);
        uint64_t w01 = pk(w.x, w.y), w23 = pk(w.z, w.w);
        #pragma unroll
        for (int i = 0; i < NI; i++){
            float qv = inb[i*4*ISTR + k];
            uint64_t qq = pk(qv, qv);
            fma2(a01[i], w01, qq);
            fma2(a23[i], w23, qq);
        }
    }
}

#define ZA(a01,a23) { _Pragma("unroll") for(int _i=0;_i<4;_i++){ a01[_i]=0; a23[_i]=0; } }

// ---------------------------------------------------------------------------
// K1: q = src @ w_qs^T ; qW[h] = (q_h @ W_k,h) * 0.125   (16 batches/CTA)
// Head stage: w_ks rows ARE the contraction dim -> dgemv on raw w_ks.
// ---------------------------------------------------------------------------
__global__ void __launch_bounds__(256) k1_qw(const float* __restrict__ src,
                                             const float* __restrict__ w_ks,
                                             int B)
{
    float* src_s = s_dyn;            // 16*ISTR = 4160
    float* q_s   = s_dyn + 4160;     // 4160
    int t  = threadIdx.x;
    int b0 = blockIdx.x * NB;
    int hcg = t & 63, hbg = t >> 6;
    int c0 = hcg * 4;

    #pragma unroll
    for (int p = 0; p < 4; p++){
        int u = p*256 + t;
        int b = u >> 6, k4 = u & 63;
        cp16(src_s + b*ISTR + k4*4, src + (size_t)b0*256 + u*4);
    }
    CP_COMMIT();
    CP_WAIT(0);
    __syncthreads();

    uint64_t a01[4], a23[4];
    ZA(a01, a23);
    dgemv<4,256>((const float4*)g_wqs_t + hcg, src_s + hbg*ISTR, a01, a23);
    #pragma unroll
    for (int i = 0; i < 4; i++)
        *(float4*)(q_s + (i*4 + hbg)*ISTR + c0) =
            make_float4(lo32(a01[i]), hi32(a01[i]), lo32(a23[i]), hi32(a23[i]));
    __syncthreads();

    #pragma unroll
    for (int h = 0; h < 4; h++){
        ZA(a01, a23);
        dgemv<4,64>((const float4*)(w_ks + (size_t)h*64*256) + hcg,
                    q_s + hbg*ISTR + h*64, a01, a23);
        #pragma unroll
        for (int i = 0; i < 4; i++)
            *(float4*)(g_qW + (size_t)(b0 + i*4 + hbg)*1024 + h*256 + c0) =
                make_float4(lo32(a01[i])*0.125f, hi32(a01[i])*0.125f,
                            lo32(a23[i])*0.125f, hi32(a23[i])*0.125f);
    }
}

// ---------------------------------------------------------------------------
// K2: flash-style attention, qW operand register-resident. (unchanged, proven)
// ---------------------------------------------------------------------------
__device__ __forceinline__ void k2_issue(float* dst, const float* gsrc, int t){
    #pragma unroll
    for (int j = 0; j < 8; j++){
        int seg = j*256 + t;
        cp16(dst + seg*4, gsrc + seg*4);
    }
    CP_COMMIT();
}

__global__ void __launch_bounds__(256, 3) k2_attn(const float* __restrict__ seq,
                                                  const void* __restrict__ mask,
                                                  int B,
                                                  float* __restrict__ attn_out)
{
    float* chk0 = s_dyn;            // 8192
    float* chk1 = s_dyn + 8192;     // 8192
    float* sc_s = s_dyn + 16384;    // 512
    float* e_s  = s_dyn + 16896;    // 128 [n][h]
    float* m_s  = s_dyn + 17024;    // 4
    float* s_s  = s_dyn + 17028;    // 4
    float* r_s  = s_dyn + 17032;    // 4 (+pad)
    __shared__ int s_u8;

    int t = threadIdx.x, b = blockIdx.x;
    int w = t >> 5, lane = t & 31;

    if (t == 0) s_u8 = 0;
    __syncthreads();
    { unsigned wv = ((const unsigned*)mask)[t]; if (wv > 1u) atomicOr(&s_u8, 1); }

    uint64_t q[4][4];
    {
        const ulonglong2* qp = (const ulonglong2*)(g_qW + (size_t)b*1024 + lane*8);
        #pragma unroll
        for (int h = 0; h < 4; h++){
            ulonglong2 v0 = qp[h*64];
            ulonglong2 v1 = qp[h*64 + 1];
            q[h][0] = v0.x; q[h][1] = v0.y; q[h][2] = v1.x; q[h][3] = v1.y;
        }
    }
    if (t < 4){ m_s[t] = -1e30f; s_s[t] = 0.f; r_s[t] = 1.f; }

    const float* gseq = seq + (size_t)b*32768;
    k2_issue(chk0, gseq, t);
    k2_issue(chk1, gseq + 8192, t);

    uint64_t c01 = 0, c23 = 0;
    int is_u8 = 0;

    #pragma unroll
    for (int c = 0; c < 4; c++){
        if (c < 3) CP_WAIT(1); else CP_WAIT(0);
        __syncthreads();
        if (c == 0) is_u8 = s_u8;
        const float* cb = (c & 1) ? chk1 : chk0;

        #pragma unroll
        for (int r = 0; r < 4; r++){
            int nl = r*8 + w;
            int ng = c*32 + nl;
            const float* vp = cb + nl*256 + lane*8;
            uint64_t v0, v1, v2, v3;
            ldsv2(v0, v1, vp);
            ldsv2(v2, v3, vp + 4);
            float sc4[4];
            #pragma unroll
            for (int h = 0; h < 4; h++){
                uint64_t a = 0;
                fma2(a, v0, q[h][0]); fma2(a, v1, q[h][1]);
                fma2(a, v2, q[h][2]); fma2(a, v3, q[h][3]);
                sc4[h] = lo32(a) + hi32(a);
            }
            #pragma unroll
            for (int o = 16; o > 0; o >>= 1){
                #pragma unroll
                for (int h = 0; h < 4; h++)
                    sc4[h] += __shfl_xor_sync(0xffffffffu, sc4[h], o);
            }
            if (lane < 4){
                int h = lane;
                int mrow = (4*b + h) % B;
                int mv = is_u8 ? (int)((const unsigned char*)mask)[(size_t)mrow*128 + ng]
                               : ((const int*)mask)[(size_t)mrow*128 + ng];
                sc_s[h*128 + ng] = mv ? -1e10f : sc4[h];
            }
        }
        __syncthreads();

        if (w < 4){
            int h = w;
            float s = sc_s[h*128 + c*32 + lane];
            float m = s;
            #pragma unroll
            for (int o = 16; o > 0; o >>= 1) m = fmaxf(m, __shfl_xor_sync(0xffffffffu, m, o));
            float Mold = m_s[h];
            float Mnew = fmaxf(Mold, m);
            float e = expf(s - Mnew);
            float ss = e;
            #pragma unroll
            for (int o = 16; o > 0; o >>= 1) ss += __shfl_xor_sync(0xffffffffu, ss, o);
            e_s[lane*4 + h] = e;
            if (lane == 0){
                float rr = expf(Mold - Mnew);
                m_s[h] = Mnew;
                s_s[h] = s_s[h]*rr + ss;
                r_s[h] = rr;
            }
        }
        __syncthreads();

        {
            uint64_t r01 = *(const uint64_t*)(r_s);
            uint64_t r23 = *(const uint64_t*)(r_s + 2);
            mul2(c01, r01);
            mul2(c23, r23);
            #pragma unroll 8
            for (int n = 0; n < 32; n++){
                float sv = cb[n*256 + t];
                uint64_t svv = pk(sv, sv);
                uint64_t e01 = *(const uint64_t*)(e_s + n*4);
                uint64_t e23 = *(const uint64_t*)(e_s + n*4 + 2);
                fma2(c01, svv, e01);
                fma2(c23, svv, e23);
            }
        }
        __syncthreads();
        if (c < 2) k2_issue((c & 1) ? chk1 : chk0, gseq + (size_t)(c+2)*8192, t);
    }

    float i0 = 1.f/s_s[0], i1 = 1.f/s_s[1], i2 = 1.f/s_s[2], i3 = 1.f/s_s[3];
    float* cbg = g_ctx + (size_t)b*1024;
    cbg[t]        = lo32(c01) * i0;
    cbg[256 + t]  = hi32(c01) * i1;
    cbg[512 + t]  = lo32(c23) * i2;
    cbg[768 + t]  = hi32(c23) * i3;

    if (attn_out){
        float invs[4] = {i0, i1, i2, i3};
        #pragma unroll
        for (int k = 0; k < 2; k++){
            int idx = k*256 + t;
            int h = idx >> 7;
            attn_out[(size_t)b*512 + idx] = expf(sc_s[idx] - m_s[h]) * invs[h];
        }
    }
}

// ---------------------------------------------------------------------------
// K3: out-proj (W_v) -> fc (+bias +residual) -> LN -> fc1(concat)+relu -> fc2
// All stages via direct-LDG dgemv on transposed weights. 16 batches/CTA.
// ---------------------------------------------------------------------------
__global__ void __launch_bounds__(256) k3_tail(const float* __restrict__ src,
        const float* __restrict__ fc_b,
        const float* __restrict__ ln_g,  const float* __restrict__ ln_b,
        const float* __restrict__ fc1_b, const float* __restrict__ fc2_b,
        float* __restrict__ out)
{
    float* ctx_s = s_dyn;                 // 4*CTXH = 16640
    float* src_s = s_dyn + 16640;         // 4160
    float* o_s   = s_dyn + 20800;         // 4160
    float* x_s   = s_dyn + 24960;         // 4160
    float* h1_s  = s_dyn + 29120;         // 4160
    float* mu_s  = s_dyn + 33280;         // 16
    float* rs_s  = s_dyn + 33296;         // 16  -> 33312 floats = 130.1KB
    int t  = threadIdx.x;
    int b0 = blockIdx.x * NB;
    int hcg = t & 63, hbg = t >> 6;
    int c0 = hcg * 4;

    #pragma unroll
    for (int p = 0; p < 16; p++){
        int u = p*256 + t;
        int b = u >> 8, rem = u & 255, h = rem >> 6, k4 = rem & 63;
        cp16(ctx_s + h*CTXH + b*ISTR + k4*4, g_ctx + (size_t)b0*1024 + u*4);
    }
    #pragma unroll
    for (int p = 0; p < 4; p++){
        int u = p*256 + t;
        int b = u >> 6, k4 = u & 63;
        cp16(src_s + b*ISTR + k4*4, src + (size_t)b0*256 + u*4);
    }
    CP_COMMIT();
    CP_WAIT(0);
    __syncthreads();

    uint64_t a01[4], a23[4];

    // ---- out projection: col quad uses ctx head hcg>>4 ----
    ZA(a01, a23);
    dgemv<4,256>((const float4*)g_wvs_t + hcg,
                 ctx_s + (hcg >> 4)*CTXH + hbg*ISTR, a01, a23);
    #pragma unroll
    for (int i = 0; i < 4; i++)
        *(float4*)(o_s + (i*4 + hbg)*ISTR + c0) =
            make_float4(lo32(a01[i]), hi32(a01[i]), lo32(a23[i]), hi32(a23[i]));
    __syncthreads();

    // ---- fc + bias + residual -> x ----
    ZA(a01, a23);
    dgemv<4,256>((const float4*)g_fcw_t + hcg, o_s + hbg*ISTR, a01, a23);
    {
        float4 fb = *(const float4*)(fc_b + c0);
        #pragma unroll
        for (int i = 0; i < 4; i++){
            int bi = i*4 + hbg;
            float4 sv = *(const float4*)(src_s + bi*ISTR + c0);
            *(float4*)(x_s + bi*ISTR + c0) =
                make_float4(lo32(a01[i]) + fb.x + sv.x, hi32(a01[i]) + fb.y + sv.y,
                            lo32(a23[i]) + fb.z + sv.z, hi32(a23[i]) + fb.w + sv.w);
        }
    }
    __syncthreads();

    // ---- LayerNorm (warp w handles rows 2w, 2w+1) ----
    {
        int w = t >> 5, lane = t & 31;
        #pragma unroll
        for (int rr = 0; rr < 2; rr++){
            int i = w*2 + rr;
            float s = 0.f, s2 = 0.f;
            const float4* xr = (const float4*)(x_s + i*ISTR + lane*8);
            #pragma unroll
            for (int qq = 0; qq < 2; qq++){
                float4 v = xr[qq];
                s  += v.x + v.y + v.z + v.w;
                s2 += v.x*v.x + v.y*v.y + v.z*v.z + v.w*v.w;
            }
            #pragma unroll
            for (int o = 16; o > 0; o >>= 1){
                s  += __shfl_xor_sync(0xffffffffu, s,  o);
                s2 += __shfl_xor_sync(0xffffffffu, s2, o);
            }
            if (lane == 0){
                float mu  = s * (1.f/256.f);
                float var = s2 * (1.f/256.f) - mu*mu;
                mu_s[i] = mu;
                rs_s[i] = rsqrtf(var + 1e-5f);
            }
        }
    }
    __syncthreads();
    {
        float g = ln_g[t], be = ln_b[t];
        #pragma unroll
        for (int i = 0; i < NB; i++)
            x_s[i*ISTR + t] = (x_s[i*ISTR + t] - mu_s[i]) * rs_s[i] * g + be;
    }
    __syncthreads();

    // ---- fc1 on concat([x, src]) + relu -> h1 ----
    ZA(a01, a23);
    dgemv<4,256>((const float4*)g_fc1_t + hcg,             x_s   + hbg*ISTR, a01, a23);
    dgemv<4,256>((const float4*)(g_fc1_t + 256*256) + hcg, src_s + hbg*ISTR, a01, a23);
    {
        float4 b1 = *(const float4*)(fc1_b + c0);
        #pragma unroll
        for (int i = 0; i < 4; i++)
            *(float4*)(h1_s + (i*4 + hbg)*ISTR + c0) =
                make_float4(fmaxf(lo32(a01[i]) + b1.x, 0.f), fmaxf(hi32(a01[i]) + b1.y, 0.f),
                            fmaxf(lo32(a23[i]) + b1.z, 0.f), fmaxf(hi32(a23[i]) + b1.w, 0.f));
    }
    __syncthreads();

    // ---- fc2 -> z ----
    ZA(a01, a23);
    dgemv<4,256>((const float4*)g_fc2_t + hcg, h1_s + hbg*ISTR, a01, a23);
    {
        float4 b2 = *(const float4*)(fc2_b + c0);
        #pragma unroll
        for (int i = 0; i < 4; i++)
            *(float4*)(out + (size_t)(b0 + i*4 + hbg)*256 + c0) =
                make_float4(lo32(a01[i]) + b2.x, hi32(a01[i]) + b2.y,
                            lo32(a23[i]) + b2.z, hi32(a23[i]) + b2.w);
    }
}

// ---------------------------------------------------------------------------
extern "C" void kernel_launch(void* const* d_in, const int* in_sizes, int n_in,
                              void* d_out, int out_size)
{
    const float* src   = (const float*)d_in[0];
    const float* seq   = (const float*)d_in[1];
    const void*  mask  = d_in[2];
    const float* w_qs  = (const float*)d_in[3];
    const float* w_ks  = (const float*)d_in[4];
    const float* w_vs  = (const float*)d_in[5];
    const float* fc_w  = (const float*)d_in[6];
    const float* fc_b  = (const float*)d_in[7];
    const float* ln_g  = (const float*)d_in[8];
    const float* ln_b  = (const float*)d_in[9];
    const float* fc1_w = (const float*)d_in[10];
    const float* fc1_b = (const float*)d_in[11];
    const float* fc2_w = (const float*)d_in[12];
    const float* fc2_b = (const float*)d_in[13];

    int B = in_sizes[0] / 256;
    if (B > MAXB) B = MAXB;

    float* z = (float*)d_out;
    float* attn_out = nullptr;
    if (out_size >= B*256 + B*512) attn_out = z + (size_t)B*256;

    size_t smem1 = (size_t)(8320)  * sizeof(float);   // 32.5KB
    size_t smem2 = (size_t)(17040) * sizeof(float);   // ~66.6KB
    size_t smem3 = (size_t)(33312) * sizeof(float);   // ~130.1KB
    cudaFuncSetAttribute(k1_qw,   cudaFuncAttributeMaxDynamicSharedMemorySize, (int)smem1);
    cudaFuncSetAttribute(k2_attn, cudaFuncAttributeMaxDynamicSharedMemorySize, (int)smem2);
    cudaFuncSetAttribute(k3_tail, cudaFuncAttributeMaxDynamicSharedMemorySize, (int)smem3);

    tr_all <<<384,  256>>>(w_qs, w_vs, fc_w, fc1_w, fc2_w);
    k1_qw  <<<B/NB, 256, smem1>>>(src, w_ks, B);
    k2_attn<<<B,    256, smem2>>>(seq, mask, B, attn_out);
    k3_tail<<<B/NB, 256, smem3>>>(src, fc_b, ln_g, ln_b, fc1_b, fc2_b, z);
}

// round 11
// speedup vs baseline: 2.1865x; 2.1865x over previous
#include <cuda_runtime.h>
#include <cstdint>

#define MAXB 2048

__device__ float g_qW[MAXB * 1024];   // (q_h @ W_k,h)/TEMP  [b][h][j]
__device__ float g_ctx[MAXB * 1024];  // attn @ seq          [b][h][j]
__device__ float g_q  [MAXB * 256];
__device__ float g_o  [MAXB * 256];
__device__ float g_x  [MAXB * 256];
__device__ float g_h1 [MAXB * 256];
// transposed weights Wt[k][c] (c contiguous, 256 cols)
__device__ float g_wqs_t[256*256];
__device__ float g_wvs_t[256*256];
__device__ float g_fcw_t[256*256];
__device__ float g_fc2_t[256*256];
__device__ float g_fc1_t[512*256];

extern __shared__ float s_dyn[];

// ---------------- helpers ----------------
__device__ __forceinline__ uint64_t pk(float x, float y){
    uint64_t r; asm("mov.b64 %0, {%1,%2};" : "=l"(r) : "f"(x), "f"(y)); return r;
}
__device__ __forceinline__ float lo32(uint64_t v){ return __uint_as_float((unsigned)(v & 0xffffffffu)); }
__device__ __forceinline__ float hi32(uint64_t v){ return __uint_as_float((unsigned)(v >> 32)); }
__device__ __forceinline__ void fma2(uint64_t& d, uint64_t a, uint64_t b){
    asm("fma.rn.f32x2 %0, %1, %2, %0;" : "+l"(d) : "l"(a), "l"(b));
}
__device__ __forceinline__ void mul2(uint64_t& d, uint64_t r){
    asm("mul.rn.f32x2 %0, %1, %2;" : "=l"(d) : "l"(d), "l"(r));
}
__device__ __forceinline__ void ldsv2(uint64_t& a, uint64_t& b, const float* p){
    uint32_t sp = (uint32_t)__cvta_generic_to_shared(p);
    asm volatile("ld.shared.v2.u64 {%0,%1}, [%2];" : "=l"(a), "=l"(b) : "r"(sp));
}
__device__ __forceinline__ void cp16(float* dst, const float* src){
    uint32_t s = (uint32_t)__cvta_generic_to_shared(dst);
    asm volatile("cp.async.cg.shared.global [%0], [%1], 16;" :: "r"(s), "l"(src));
}
#define CP_COMMIT() asm volatile("cp.async.commit_group;" ::: "memory")
#define CP_WAIT(N)  asm volatile("cp.async.wait_group %0;" :: "n"(N) : "memory")

// ---------------------------------------------------------------------------
// Weight transpose: Wt[k][c] = W[c][k].  32x32 smem tiles. (verified R10)
// ---------------------------------------------------------------------------
__global__ void __launch_bounds__(256) tr_all(const float* __restrict__ w_qs,
                                              const float* __restrict__ w_vs,
                                              const float* __restrict__ fc_w,
                                              const float* __restrict__ fc1_w,
                                              const float* __restrict__ fc2_w)
{
    __shared__ float ts[32][33];
    int id = blockIdx.x;
    const float* src; float* dst; int K, tile;
    if      (id < 64) { src = w_qs;  dst = g_wqs_t; K = 256; tile = id; }
    else if (id < 128){ src = w_vs;  dst = g_wvs_t; K = 256; tile = id - 64; }
    else if (id < 192){ src = fc_w;  dst = g_fcw_t; K = 256; tile = id - 128; }
    else if (id < 320){ src = fc1_w; dst = g_fc1_t; K = 512; tile = id - 192; }
    else              { src = fc2_w; dst = g_fc2_t; K = 256; tile = id - 320; }
    int ntk = K >> 5;
    int tc = tile / ntk, tk = tile % ntk;
    int c0 = tc*32, k0 = tk*32;
    int tx = threadIdx.x & 31, ty = threadIdx.x >> 5;
    #pragma unroll
    for (int r = 0; r < 32; r += 8)
        ts[ty + r][tx] = src[(size_t)(c0 + ty + r)*K + k0 + tx];
    __syncthreads();
    #pragma unroll
    for (int r = 0; r < 32; r += 8)
        dst[(size_t)(k0 + ty + r)*256 + c0 + tx] = ts[tx][ty + r];
}

// ---------------------------------------------------------------------------
// Tiled SGEMM: C[M,*] = epi( A[M,K] @ Bt[K,*] )     (Bt k-major, c contiguous)
// CTA tile 32 m x 64 c, 256 threads, thread tile 2m x 4c, K-slab 16, cp.async
// double buffered. AMODE: 0 plain; 1 per-head qW (A col off (ct>>2)*64,
// B = w_ks + (ct>>2)*64*256, bcoff (ct&3)*64, K=64); 2 ctx out-proj (A off
// ct*256, lda 1024); 3 concat (A for k<256, A2 after).
// EPI: 0 none; 1 *0.125; 2 +bias+resid; 3 relu(+bias); 4 +bias.
// ---------------------------------------------------------------------------
template<int KTOT, int AMODE, int EPI>
__global__ void __launch_bounds__(256) sgemm(
    const float* __restrict__ A, const float* __restrict__ A2, int lda,
    const float* __restrict__ Bt, float* __restrict__ C, int ldc,
    const float* __restrict__ bias, const float* __restrict__ resid)
{
    __shared__ float As[2][32][20];
    __shared__ float Bs[2][16][64];
    int t  = threadIdx.x;
    int ct = blockIdx.x, bt = blockIdx.y;
    int bm0 = bt * 32;
    int tx = t & 15, ty = t >> 4;
    int m0 = ty * 2;

    const float* Ab; const float* Bb; int bcoff;
    if (AMODE == 1){ Ab = A + (ct>>2)*64;  Bb = Bt + (size_t)(ct>>2)*64*256; bcoff = (ct&3)*64; }
    else if (AMODE == 2){ Ab = A + ct*256; Bb = Bt; bcoff = ct*64; }
    else { Ab = A; Bb = Bt; bcoff = ct*64; }

    auto issue = [&](int j){
        int k0 = j * 16;
        const float* Ap = Ab; int k0a = k0;
        if (AMODE == 3 && k0 >= 256){ Ap = A2 + (size_t)0; k0a = k0 - 256; }
        if (t < 128){
            int m = t >> 2, kc = t & 3;
            cp16(&As[j&1][m][kc*4], Ap + (size_t)(bm0+m)*lda + k0a + kc*4);
        }
        {
            int kb = t >> 4, cu = t & 15;
            cp16(&Bs[j&1][kb][cu*4], Bb + (size_t)(k0+kb)*256 + bcoff + cu*4);
        }
        CP_COMMIT();
    };

    uint64_t a01[2] = {0,0}, a23[2] = {0,0};
    constexpr int NS = KTOT / 16;
    issue(0);
    if (NS > 1) issue(1);
    for (int j = 0; j < NS; j++){
        if (j < NS-1) CP_WAIT(1); else CP_WAIT(0);
        __syncthreads();
        int buf = j & 1;
        #pragma unroll
        for (int kk = 0; kk < 16; kk++){
            ulonglong2 b4 = *(const ulonglong2*)(&Bs[buf][kk][tx*4]);
            float x0 = As[buf][m0][kk];
            float x1 = As[buf][m0+1][kk];
            uint64_t d0 = pk(x0, x0), d1 = pk(x1, x1);
            fma2(a01[0], b4.x, d0); fma2(a23[0], b4.y, d0);
            fma2(a01[1], b4.x, d1); fma2(a23[1], b4.y, d1);
        }
        __syncthreads();
        if (j + 2 < NS) issue(j + 2);
    }

    int cg = ct*64 + tx*4;
    #pragma unroll
    for (int i = 0; i < 2; i++){
        int mg = bm0 + m0 + i;
        float4 v = make_float4(lo32(a01[i]), hi32(a01[i]),
                               lo32(a23[i]), hi32(a23[i]));
        if (EPI == 1){ v.x *= 0.125f; v.y *= 0.125f; v.z *= 0.125f; v.w *= 0.125f; }
        if (EPI >= 2){
            float4 bb = *(const float4*)(bias + cg);
            v.x += bb.x; v.y += bb.y; v.z += bb.z; v.w += bb.w;
        }
        if (EPI == 2){
            float4 rr = *(const float4*)(resid + (size_t)mg*256 + cg);
            v.x += rr.x; v.y += rr.y; v.z += rr.z; v.w += rr.w;
        }
        if (EPI == 3){
            v.x = fmaxf(v.x, 0.f); v.y = fmaxf(v.y, 0.f);
            v.z = fmaxf(v.z, 0.f); v.w = fmaxf(v.w, 0.f);
        }
        *(float4*)(C + (size_t)mg*ldc + cg) = v;
    }
}

// ---------------------------------------------------------------------------
// LayerNorm in-place on x[B,256]; one warp per row.
// ---------------------------------------------------------------------------
__global__ void __launch_bounds__(256) ln_k(float* __restrict__ x,
                                            const float* __restrict__ ln_g,
                                            const float* __restrict__ ln_b)
{
    int w = threadIdx.x >> 5, lane = threadIdx.x & 31;
    int r = blockIdx.x*8 + w;
    float* xr = x + (size_t)r*256 + lane*8;
    float4 v0 = *(const float4*)xr;
    float4 v1 = *(const float4*)(xr + 4);
    float s  = v0.x+v0.y+v0.z+v0.w + v1.x+v1.y+v1.z+v1.w;
    float s2 = v0.x*v0.x+v0.y*v0.y+v0.z*v0.z+v0.w*v0.w
             + v1.x*v1.x+v1.y*v1.y+v1.z*v1.z+v1.w*v1.w;
    #pragma unroll
    for (int o = 16; o > 0; o >>= 1){
        s  += __shfl_xor_sync(0xffffffffu, s,  o);
        s2 += __shfl_xor_sync(0xffffffffu, s2, o);
    }
    float mu = s * (1.f/256.f);
    float rs = rsqrtf(s2 * (1.f/256.f) - mu*mu + 1e-5f);
    float4 g0 = *(const float4*)(ln_g + lane*8);
    float4 g1 = *(const float4*)(ln_g + lane*8 + 4);
    float4 b0 = *(const float4*)(ln_b + lane*8);
    float4 b1 = *(const float4*)(ln_b + lane*8 + 4);
    v0.x = (v0.x-mu)*rs*g0.x + b0.x; v0.y = (v0.y-mu)*rs*g0.y + b0.y;
    v0.z = (v0.z-mu)*rs*g0.z + b0.z; v0.w = (v0.w-mu)*rs*g0.w + b0.w;
    v1.x = (v1.x-mu)*rs*g1.x + b1.x; v1.y = (v1.y-mu)*rs*g1.y + b1.y;
    v1.z = (v1.z-mu)*rs*g1.z + b1.z; v1.w = (v1.w-mu)*rs*g1.w + b1.w;
    *(float4*)xr = v0;
    *(float4*)(xr + 4) = v1;
}

// ---------------------------------------------------------------------------
// K2: flash-style attention, qW register-resident. (unchanged, proven)
// ---------------------------------------------------------------------------
__device__ __forceinline__ void k2_issue(float* dst, const float* gsrc, int t){
    #pragma unroll
    for (int j = 0; j < 8; j++){
        int seg = j*256 + t;
        cp16(dst + seg*4, gsrc + seg*4);
    }
    CP_COMMIT();
}

__global__ void __launch_bounds__(256, 3) k2_attn(const float* __restrict__ seq,
                                                  const void* __restrict__ mask,
                                                  int B,
                                                  float* __restrict__ attn_out)
{
    float* chk0 = s_dyn;            // 8192
    float* chk1 = s_dyn + 8192;     // 8192
    float* sc_s = s_dyn + 16384;    // 512
    float* e_s  = s_dyn + 16896;    // 128 [n][h]
    float* m_s  = s_dyn + 17024;    // 4
    float* s_s  = s_dyn + 17028;    // 4
    float* r_s  = s_dyn + 17032;    // 4 (+pad)
    __shared__ int s_u8;

    int t = threadIdx.x, b = blockIdx.x;
    int w = t >> 5, lane = t & 31;

    if (t == 0) s_u8 = 0;
    __syncthreads();
    { unsigned wv = ((const unsigned*)mask)[t]; if (wv > 1u) atomicOr(&s_u8, 1); }

    uint64_t q[4][4];
    {
        const ulonglong2* qp = (const ulonglong2*)(g_qW + (size_t)b*1024 + lane*8);
        #pragma unroll
        for (int h = 0; h < 4; h++){
            ulonglong2 v0 = qp[h*64];
            ulonglong2 v1 = qp[h*64 + 1];
            q[h][0] = v0.x; q[h][1] = v0.y; q[h][2] = v1.x; q[h][3] = v1.y;
        }
    }
    if (t < 4){ m_s[t] = -1e30f; s_s[t] = 0.f; r_s[t] = 1.f; }

    const float* gseq = seq + (size_t)b*32768;
    k2_issue(chk0, gseq, t);
    k2_issue(chk1, gseq + 8192, t);

    uint64_t c01 = 0, c23 = 0;
    int is_u8 = 0;

    #pragma unroll
    for (int c = 0; c < 4; c++){
        if (c < 3) CP_WAIT(1); else CP_WAIT(0);
        __syncthreads();
        if (c == 0) is_u8 = s_u8;
        const float* cb = (c & 1) ? chk1 : chk0;

        #pragma unroll
        for (int r = 0; r < 4; r++){
            int nl = r*8 + w;
            int ng = c*32 + nl;
            const float* vp = cb + nl*256 + lane*8;
            uint64_t v0, v1, v2, v3;
            ldsv2(v0, v1, vp);
            ldsv2(v2, v3, vp + 4);
            float sc4[4];
            #pragma unroll
            for (int h = 0; h < 4; h++){
                uint64_t a = 0;
                fma2(a, v0, q[h][0]); fma2(a, v1, q[h][1]);
                fma2(a, v2, q[h][2]); fma2(a, v3, q[h][3]);
                sc4[h] = lo32(a) + hi32(a);
            }
            #pragma unroll
            for (int o = 16; o > 0; o >>= 1){
                #pragma unroll
                for (int h = 0; h < 4; h++)
                    sc4[h] += __shfl_xor_sync(0xffffffffu, sc4[h], o);
            }
            if (lane < 4){
                int h = lane;
                int mrow = (4*b + h) % B;
                int mv = is_u8 ? (int)((const unsigned char*)mask)[(size_t)mrow*128 + ng]
                               : ((const int*)mask)[(size_t)mrow*128 + ng];
                sc_s[h*128 + ng] = mv ? -1e10f : sc4[h];
            }
        }
        __syncthreads();

        if (w < 4){
            int h = w;
            float s = sc_s[h*128 + c*32 + lane];
            float m = s;
            #pragma unroll
            for (int o = 16; o > 0; o >>= 1) m = fmaxf(m, __shfl_xor_sync(0xffffffffu, m, o));
            float Mold = m_s[h];
            float Mnew = fmaxf(Mold, m);
            float e = expf(s - Mnew);
            float ss = e;
            #pragma unroll
            for (int o = 16; o > 0; o >>= 1) ss += __shfl_xor_sync(0xffffffffu, ss, o);
            e_s[lane*4 + h] = e;
            if (lane == 0){
                float rr = expf(Mold - Mnew);
                m_s[h] = Mnew;
                s_s[h] = s_s[h]*rr + ss;
                r_s[h] = rr;
            }
        }
        __syncthreads();

        {
            uint64_t r01 = *(const uint64_t*)(r_s);
            uint64_t r23 = *(const uint64_t*)(r_s + 2);
            mul2(c01, r01);
            mul2(c23, r23);
            #pragma unroll 8
            for (int n = 0; n < 32; n++){
                float sv = cb[n*256 + t];
                uint64_t svv = pk(sv, sv);
                uint64_t e01 = *(const uint64_t*)(e_s + n*4);
                uint64_t e23 = *(const uint64_t*)(e_s + n*4 + 2);
                fma2(c01, svv, e01);
                fma2(c23, svv, e23);
            }
        }
        __syncthreads();
        if (c < 2) k2_issue((c & 1) ? chk1 : chk0, gseq + (size_t)(c+2)*8192, t);
    }

    float i0 = 1.f/s_s[0], i1 = 1.f/s_s[1], i2 = 1.f/s_s[2], i3 = 1.f/s_s[3];
    float* cbg = g_ctx + (size_t)b*1024;
    cbg[t]        = lo32(c01) * i0;
    cbg[256 + t]  = hi32(c01) * i1;
    cbg[512 + t]  = lo32(c23) * i2;
    cbg[768 + t]  = hi32(c23) * i3;

    if (attn_out){
        float invs[4] = {i0, i1, i2, i3};
        #pragma unroll
        for (int k = 0; k < 2; k++){
            int idx = k*256 + t;
            int h = idx >> 7;
            attn_out[(size_t)b*512 + idx] = expf(sc_s[idx] - m_s[h]) * invs[h];
        }
    }
}

// ---------------------------------------------------------------------------
extern "C" void kernel_launch(void* const* d_in, const int* in_sizes, int n_in,
                              void* d_out, int out_size)
{
    const float* src   = (const float*)d_in[0];
    const float* seq   = (const float*)d_in[1];
    const void*  mask  = d_in[2];
    const float* w_qs  = (const float*)d_in[3];
    const float* w_ks  = (const float*)d_in[4];
    const float* w_vs  = (const float*)d_in[5];
    const float* fc_w  = (const float*)d_in[6];
    const float* fc_b  = (const float*)d_in[7];
    const float* ln_g  = (const float*)d_in[8];
    const float* ln_b  = (const float*)d_in[9];
    const float* fc1_w = (const float*)d_in[10];
    const float* fc1_b = (const float*)d_in[11];
    const float* fc2_w = (const float*)d_in[12];
    const float* fc2_b = (const float*)d_in[13];

    int B = in_sizes[0] / 256;
    if (B > MAXB) B = MAXB;

    float* z = (float*)d_out;
    float* attn_out = nullptr;
    if (out_size >= B*256 + B*512) attn_out = z + (size_t)B*256;

    size_t smem2 = (size_t)(17040) * sizeof(float);   // ~66.6KB
    cudaFuncSetAttribute(k2_attn, cudaFuncAttributeMaxDynamicSharedMemorySize, (int)smem2);

    float* gq  = nullptr; cudaGetSymbolAddress((void**)&gq,  g_q);
    float* gqW = nullptr; cudaGetSymbolAddress((void**)&gqW, g_qW);
    float* gcx = nullptr; cudaGetSymbolAddress((void**)&gcx, g_ctx);
    float* go  = nullptr; cudaGetSymbolAddress((void**)&go,  g_o);
    float* gx  = nullptr; cudaGetSymbolAddress((void**)&gx,  g_x);
    float* gh1 = nullptr; cudaGetSymbolAddress((void**)&gh1, g_h1);
    float* wqs_t = nullptr; cudaGetSymbolAddress((void**)&wqs_t, g_wqs_t);
    float* wvs_t = nullptr; cudaGetSymbolAddress((void**)&wvs_t, g_wvs_t);
    float* fcw_t = nullptr; cudaGetSymbolAddress((void**)&fcw_t, g_fcw_t);
    float* fc1_t = nullptr; cudaGetSymbolAddress((void**)&fc1_t, g_fc1_t);
    float* fc2_t = nullptr; cudaGetSymbolAddress((void**)&fc2_t, g_fc2_t);

    int MB = B / 32;   // 64 batch tiles

    tr_all<<<384, 256>>>(w_qs, w_vs, fc_w, fc1_w, fc2_w);

    // G1: q = src @ w_qs^T
    sgemm<256,0,0><<<dim3(4,  MB), 256>>>(src, nullptr, 256, wqs_t, gq, 256, nullptr, nullptr);
    // G2: qW[h] = (q_h @ W_k,h) * 0.125   (K=64 per head, w_ks raw is k-major)
    sgemm<64, 1,1><<<dim3(16, MB), 256>>>(gq, nullptr, 256, (const float*)w_ks, gqW, 1024, nullptr, nullptr);
    // K2: attention
    k2_attn<<<B, 256, smem2>>>(seq, mask, B, attn_out);
    // G3: o = ctx_head @ w_vs^T
    sgemm<256,2,0><<<dim3(4,  MB), 256>>>(gcx, nullptr, 1024, wvs_t, go, 256, nullptr, nullptr);
    // G4: x = o @ fc_w^T + fc_b + src
    sgemm<256,0,2><<<dim3(4,  MB), 256>>>(go, nullptr, 256, fcw_t, gx, 256, fc_b, src);
    // LN in place
    ln_k<<<B/8, 256>>>(gx, ln_g, ln_b);
    // G5: h1 = relu([x, src] @ fc1^T + fc1_b)   (K=512, A switches at 256)
    sgemm<512,3,3><<<dim3(4,  MB), 256>>>(gx, src, 256, fc1_t, gh1, 256, fc1_b, nullptr);
    // G6: z = h1 @ fc2^T + fc2_b
    sgemm<256,0,4><<<dim3(4,  MB), 256>>>(gh1, nullptr, 256, fc2_t, z, 256, fc2_b, nullptr);
}

// round 12
// speedup vs baseline: 2.4399x; 1.1159x over previous
#include <cuda_runtime.h>
#include <cstdint>

#define MAXB 2048

__device__ float g_qW[MAXB * 1024];   // (q_h @ W_k,h)/TEMP  [b][h][j]
__device__ float g_ctx[MAXB * 1024];  // attn @ seq          [b][h][j]
__device__ float g_q  [MAXB * 256];
__device__ float g_o  [MAXB * 256];
__device__ float g_x  [MAXB * 256];
__device__ float g_h1 [MAXB * 256];
// transposed weights Wt[k][c] (c contiguous, 256 cols)
__device__ float g_wqs_t[256*256];
__device__ float g_wvs_t[256*256];
__device__ float g_fcw_t[256*256];
__device__ float g_fc2_t[256*256];
__device__ float g_fc1_t[512*256];

// ---------------- helpers ----------------
__device__ __forceinline__ uint64_t pk(float x, float y){
    uint64_t r; asm("mov.b64 %0, {%1,%2};" : "=l"(r) : "f"(x), "f"(y)); return r;
}
__device__ __forceinline__ float lo32(uint64_t v){ return __uint_as_float((unsigned)(v & 0xffffffffu)); }
__device__ __forceinline__ float hi32(uint64_t v){ return __uint_as_float((unsigned)(v >> 32)); }
__device__ __forceinline__ void fma2(uint64_t& d, uint64_t a, uint64_t b){
    asm("fma.rn.f32x2 %0, %1, %2, %0;" : "+l"(d) : "l"(a), "l"(b));
}
__device__ __forceinline__ void cp16(float* dst, const float* src){
    uint32_t s = (uint32_t)__cvta_generic_to_shared(dst);
    asm volatile("cp.async.cg.shared.global [%0], [%1], 16;" :: "r"(s), "l"(src));
}
#define CP_COMMIT() asm volatile("cp.async.commit_group;" ::: "memory")
#define CP_WAIT(N)  asm volatile("cp.async.wait_group %0;" :: "n"(N) : "memory")

// ---------------------------------------------------------------------------
// Weight transpose: Wt[k][c] = W[c][k].  32x32 smem tiles. (verified)
// ---------------------------------------------------------------------------
__global__ void __launch_bounds__(256) tr_all(const float* __restrict__ w_qs,
                                              const float* __restrict__ w_vs,
                                              const float* __restrict__ fc_w,
                                              const float* __restrict__ fc1_w,
                                              const float* __restrict__ fc2_w)
{
    __shared__ float ts[32][33];
    int id = blockIdx.x;
    const float* src; float* dst; int K, tile;
    if      (id < 64) { src = w_qs;  dst = g_wqs_t; K = 256; tile = id; }
    else if (id < 128){ src = w_vs;  dst = g_wvs_t; K = 256; tile = id - 64; }
    else if (id < 192){ src = fc_w;  dst = g_fcw_t; K = 256; tile = id - 128; }
    else if (id < 320){ src = fc1_w; dst = g_fc1_t; K = 512; tile = id - 192; }
    else              { src = fc2_w; dst = g_fc2_t; K = 256; tile = id - 320; }
    int ntk = K >> 5;
    int tc = tile / ntk, tk = tile % ntk;
    int c0 = tc*32, k0 = tk*32;
    int tx = threadIdx.x & 31, ty = threadIdx.x >> 5;
    #pragma unroll
    for (int r = 0; r < 32; r += 8)
        ts[ty + r][tx] = src[(size_t)(c0 + ty + r)*K + k0 + tx];
    __syncthreads();
    #pragma unroll
    for (int r = 0; r < 32; r += 8)
        dst[(size_t)(k0 + ty + r)*256 + c0 + tx] = ts[tx][ty + r];
}

// ---------------------------------------------------------------------------
// Tiled SGEMM (verified R11): C[M,*] = epi( A[M,K] @ Bt[K,*] )
// CTA tile 32m x 64c, thread tile 2m x 4c, K-slab 16, cp.async dbl buffer.
// ---------------------------------------------------------------------------
template<int KTOT, int AMODE, int EPI>
__global__ void __launch_bounds__(256) sgemm(
    const float* __restrict__ A, const float* __restrict__ A2, int lda,
    const float* __restrict__ Bt, float* __restrict__ C, int ldc,
    const float* __restrict__ bias, const float* __restrict__ resid)
{
    __shared__ float As[2][32][20];
    __shared__ float Bs[2][16][64];
    int t  = threadIdx.x;
    int ct = blockIdx.x, bt = blockIdx.y;
    int bm0 = bt * 32;
    int tx = t & 15, ty = t >> 4;
    int m0 = ty * 2;

    const float* Ab; const float* Bb; int bcoff;
    if (AMODE == 1){ Ab = A + (ct>>2)*64;  Bb = Bt + (size_t)(ct>>2)*64*256; bcoff = (ct&3)*64; }
    else if (AMODE == 2){ Ab = A + ct*256; Bb = Bt; bcoff = ct*64; }
    else { Ab = A; Bb = Bt; bcoff = ct*64; }

    auto issue = [&](int j){
        int k0 = j * 16;
        const float* Ap = Ab; int k0a = k0;
        if (AMODE == 3 && k0 >= 256){ Ap = A2; k0a = k0 - 256; }
        if (t < 128){
            int m = t >> 2, kc = t & 3;
            cp16(&As[j&1][m][kc*4], Ap + (size_t)(bm0+m)*lda + k0a + kc*4);
        }
        {
            int kb = t >> 4, cu = t & 15;
            cp16(&Bs[j&1][kb][cu*4], Bb + (size_t)(k0+kb)*256 + bcoff + cu*4);
        }
        CP_COMMIT();
    };

    uint64_t a01[2] = {0,0}, a23[2] = {0,0};
    constexpr int NS = KTOT / 16;
    issue(0);
    if (NS > 1) issue(1);
    for (int j = 0; j < NS; j++){
        if (j < NS-1) CP_WAIT(1); else CP_WAIT(0);
        __syncthreads();
        int buf = j & 1;
        #pragma unroll
        for (int kk = 0; kk < 16; kk++){
            ulonglong2 b4 = *(const ulonglong2*)(&Bs[buf][kk][tx*4]);
            float x0 = As[buf][m0][kk];
            float x1 = As[buf][m0+1][kk];
            uint64_t d0 = pk(x0, x0), d1 = pk(x1, x1);
            fma2(a01[0], b4.x, d0); fma2(a23[0], b4.y, d0);
            fma2(a01[1], b4.x, d1); fma2(a23[1], b4.y, d1);
        }
        __syncthreads();
        if (j + 2 < NS) issue(j + 2);
    }

    int cg = ct*64 + tx*4;
    #pragma unroll
    for (int i = 0; i < 2; i++){
        int mg = bm0 + m0 + i;
        float4 v = make_float4(lo32(a01[i]), hi32(a01[i]),
                               lo32(a23[i]), hi32(a23[i]));
        if (EPI == 1){ v.x *= 0.125f; v.y *= 0.125f; v.z *= 0.125f; v.w *= 0.125f; }
        if (EPI >= 2){
            float4 bb = *(const float4*)(bias + cg);
            v.x += bb.x; v.y += bb.y; v.z += bb.z; v.w += bb.w;
        }
        if (EPI == 2){
            float4 rr = *(const float4*)(resid + (size_t)mg*256 + cg);
            v.x += rr.x; v.y += rr.y; v.z += rr.z; v.w += rr.w;
        }
        if (EPI == 3){
            v.x = fmaxf(v.x, 0.f); v.y = fmaxf(v.y, 0.f);
            v.z = fmaxf(v.z, 0.f); v.w = fmaxf(v.w, 0.f);
        }
        *(float4*)(C + (size_t)mg*ldc + cg) = v;
    }
}

// ---------------------------------------------------------------------------
// LayerNorm in-place on x[B,256]; one warp per row. (verified R11)
// ---------------------------------------------------------------------------
__global__ void __launch_bounds__(256) ln_k(float* __restrict__ x,
                                            const float* __restrict__ ln_g,
                                            const float* __restrict__ ln_b)
{
    int w = threadIdx.x >> 5, lane = threadIdx.x & 31;
    int r = blockIdx.x*8 + w;
    float* xr = x + (size_t)r*256 + lane*8;
    float4 v0 = *(const float4*)xr;
    float4 v1 = *(const float4*)(xr + 4);
    float s  = v0.x+v0.y+v0.z+v0.w + v1.x+v1.y+v1.z+v1.w;
    float s2 = v0.x*v0.x+v0.y*v0.y+v0.z*v0.z+v0.w*v0.w
             + v1.x*v1.x+v1.y*v1.y+v1.z*v1.z+v1.w*v1.w;
    #pragma unroll
    for (int o = 16; o > 0; o >>= 1){
        s  += __shfl_xor_sync(0xffffffffu, s,  o);
        s2 += __shfl_xor_sync(0xffffffffu, s2, o);
    }
    float mu = s * (1.f/256.f);
    float rs = rsqrtf(s2 * (1.f/256.f) - mu*mu + 1e-5f);
    float4 g0 = *(const float4*)(ln_g + lane*8);
    float4 g1 = *(const float4*)(ln_g + lane*8 + 4);
    float4 b0 = *(const float4*)(ln_b + lane*8);
    float4 b1 = *(const float4*)(ln_b + lane*8 + 4);
    v0.x = (v0.x-mu)*rs*g0.x + b0.x; v0.y = (v0.y-mu)*rs*g0.y + b0.y;
    v0.z = (v0.z-mu)*rs*g0.z + b0.z; v0.w = (v0.w-mu)*rs*g0.w + b0.w;
    v1.x = (v1.x-mu)*rs*g1.x + b1.x; v1.y = (v1.y-mu)*rs*g1.y + b1.y;
    v1.z = (v1.z-mu)*rs*g1.z + b1.z; v1.w = (v1.w-mu)*rs*g1.w + b1.w;
    *(float4*)xr = v0;
    *(float4*)(xr + 4) = v1;
}

// ---------------------------------------------------------------------------
// K2 v2: two-pass attention, no chunk barriers, direct coalesced LDG.
// Pass 1: scores (16 rows/warp, 6-SHFL multi-head reduce). One softmax.
// Pass 2: ctx from L1-hot seq (LDG.32 coalesced), attn broadcast from smem.
// ---------------------------------------------------------------------------
__global__ void __launch_bounds__(256, 3) k2_attn(const float* __restrict__ seq,
                                                  const void* __restrict__ mask,
                                                  int B,
                                                  float* __restrict__ attn_out)
{
    __shared__ __align__(16) float sc_s[512];   // [h][n]
    __shared__ __align__(16) float e_s[512];    // [n][h]
    __shared__ __align__(16) float msk_s[512];  // [h][n] 1=masked
    __shared__ int s_u8;

    int t = threadIdx.x, b = blockIdx.x;
    int w = t >> 5, lane = t & 31;

    if (t == 0) s_u8 = 0;
    __syncthreads();
    { unsigned wv = ((const unsigned*)mask)[t]; if (wv > 1u) atomicOr(&s_u8, 1); }
    __syncthreads();
    int is_u8 = s_u8;

    // stage mask flags (mask row (4b+h)%B — reference head-major tiling quirk)
    #pragma unroll
    for (int p = 0; p < 2; p++){
        int idx = p*256 + t;
        int h = idx >> 7, n = idx & 127;
        int mrow = (4*b + h) % B;
        int mv = is_u8 ? (int)((const unsigned char*)mask)[(size_t)mrow*128 + n]
                       : ((const int*)mask)[(size_t)mrow*128 + n];
        msk_s[idx] = mv ? 1.f : 0.f;
    }

    // qW in registers: q[h][0..3] u64 = 8 floats at lane*8
    uint64_t q[4][4];
    {
        const ulonglong2* qp = (const ulonglong2*)(g_qW + (size_t)b*1024 + lane*8);
        #pragma unroll
        for (int h = 0; h < 4; h++){
            ulonglong2 v0 = qp[h*64];
            ulonglong2 v1 = qp[h*64 + 1];
            q[h][0] = v0.x; q[h][1] = v0.y; q[h][2] = v1.x; q[h][3] = v1.y;
        }
    }
    const float* gseq = seq + (size_t)b*32768;
    __syncthreads();   // msk_s ready

    // ---- pass 1: scores, rows n = r*8 + w ----
    #pragma unroll 2
    for (int r = 0; r < 16; r++){
        int n = r*8 + w;
        const float4* vp = (const float4*)(gseq + n*256 + lane*8);
        float4 va = __ldg(vp), vb = __ldg(vp + 1);
        uint64_t u0 = pk(va.x, va.y), u1 = pk(va.z, va.w);
        uint64_t u2 = pk(vb.x, vb.y), u3 = pk(vb.z, vb.w);
        float sc4[4];
        #pragma unroll
        for (int h = 0; h < 4; h++){
            uint64_t a = 0;
            fma2(a, u0, q[h][0]); fma2(a, u1, q[h][1]);
            fma2(a, u2, q[h][2]); fma2(a, u3, q[h][3]);
            sc4[h] = lo32(a) + hi32(a);
        }
        // 6-SHFL 4-head reduce: lane ends with head (lane&3)'s full sum
        bool b0 = (lane & 1) != 0;
        float k01 = b0 ? sc4[1] : sc4[0];
        float s01 = b0 ? sc4[0] : sc4[1];
        float m01 = k01 + __shfl_xor_sync(0xffffffffu, s01, 1);
        float k23 = b0 ? sc4[3] : sc4[2];
        float s23 = b0 ? sc4[2] : sc4[3];
        float m23 = k23 + __shfl_xor_sync(0xffffffffu, s23, 1);
        bool b1 = (lane & 2) != 0;
        float kk = b1 ? m23 : m01;
        float ss = b1 ? m01 : m23;
        float sv = kk + __shfl_xor_sync(0xffffffffu, ss, 2);
        sv += __shfl_xor_sync(0xffffffffu, sv, 4);
        sv += __shfl_xor_sync(0xffffffffu, sv, 8);
        sv += __shfl_xor_sync(0xffffffffu, sv, 16);
        if (lane < 4){
            int h = lane;
            float f = msk_s[h*128 + n];
            sc_s[h*128 + n] = (f > 0.5f) ? -1e10f : sv;
        }
    }
    __syncthreads();

    // ---- one softmax: warp h < 4 handles head h ----
    if (w < 4){
        int h = w;
        float v0 = sc_s[h*128 + lane];
        float v1 = sc_s[h*128 + lane + 32];
        float v2 = sc_s[h*128 + lane + 64];
        float v3 = sc_s[h*128 + lane + 96];
        float m = fmaxf(fmaxf(v0, v1), fmaxf(v2, v3));
        #pragma unroll
        for (int o = 16; o > 0; o >>= 1) m = fmaxf(m, __shfl_xor_sync(0xffffffffu, m, o));
        float e0 = expf(v0 - m), e1 = expf(v1 - m), e2 = expf(v2 - m), e3 = expf(v3 - m);
        float s = e0 + e1 + e2 + e3;
        #pragma unroll
        for (int o = 16; o > 0; o >>= 1) s += __shfl_xor_sync(0xffffffffu, s, o);
        float inv = 1.f / s;
        e0 *= inv; e1 *= inv; e2 *= inv; e3 *= inv;
        e_s[lane*4 + h]       = e0;
        e_s[(lane+32)*4 + h]  = e1;
        e_s[(lane+64)*4 + h]  = e2;
        e_s[(lane+96)*4 + h]  = e3;
        if (attn_out){
            float* ao = attn_out + (size_t)b*512 + h*128;
            ao[lane] = e0; ao[lane+32] = e1; ao[lane+64] = e2; ao[lane+96] = e3;
        }
    }
    __syncthreads();

    // ---- pass 2: ctx[h][t] = sum_n attn[h][n] * seq[n][t]  (seq L1-hot) ----
    uint64_t c01 = 0, c23 = 0;
    const float* sp = gseq + t;
    #pragma unroll 8
    for (int n = 0; n < 128; n++){
        float sv = __ldg(sp + n*256);
        uint64_t svv = pk(sv, sv);
        uint64_t e01 = *(const uint64_t*)(e_s + n*4);
        uint64_t e23 = *(const uint64_t*)(e_s + n*4 + 2);
        fma2(c01, svv, e01);
        fma2(c23, svv, e23);
    }
    float* cbg = g_ctx + (size_t)b*1024;
    cbg[t]       = lo32(c01);
    cbg[256 + t] = hi32(c01);
    cbg[512 + t] = lo32(c23);
    cbg[768 + t] = hi32(c23);
}

// ---------------------------------------------------------------------------
extern "C" void kernel_launch(void* const* d_in, const int* in_sizes, int n_in,
                              void* d_out, int out_size)
{
    const float* src   = (const float*)d_in[0];
    const float* seq   = (const float*)d_in[1];
    const void*  mask  = d_in[2];
    const float* w_qs  = (const float*)d_in[3];
    const float* w_ks  = (const float*)d_in[4];
    const float* w_vs  = (const float*)d_in[5];
    const float* fc_w  = (const float*)d_in[6];
    const float* fc_b  = (const float*)d_in[7];
    const float* ln_g  = (const float*)d_in[8];
    const float* ln_b  = (const float*)d_in[9];
    const float* fc1_w = (const float*)d_in[10];
    const float* fc1_b = (const float*)d_in[11];
    const float* fc2_w = (const float*)d_in[12];
    const float* fc2_b = (const float*)d_in[13];

    int B = in_sizes[0] / 256;
    if (B > MAXB) B = MAXB;

    float* z = (float*)d_out;
    float* attn_out = nullptr;
    if (out_size >= B*256 + B*512) attn_out = z + (size_t)B*256;

    float* gq  = nullptr; cudaGetSymbolAddress((void**)&gq,  g_q);
    float* gqW = nullptr; cudaGetSymbolAddress((void**)&gqW, g_qW);
    float* gcx = nullptr; cudaGetSymbolAddress((void**)&gcx, g_ctx);
    float* go  = nullptr; cudaGetSymbolAddress((void**)&go,  g_o);
    float* gx  = nullptr; cudaGetSymbolAddress((void**)&gx,  g_x);
    float* gh1 = nullptr; cudaGetSymbolAddress((void**)&gh1, g_h1);
    float* wqs_t = nullptr; cudaGetSymbolAddress((void**)&wqs_t, g_wqs_t);
    float* wvs_t = nullptr; cudaGetSymbolAddress((void**)&wvs_t, g_wvs_t);
    float* fcw_t = nullptr; cudaGetSymbolAddress((void**)&fcw_t, g_fcw_t);
    float* fc1_t = nullptr; cudaGetSymbolAddress((void**)&fc1_t, g_fc1_t);
    float* fc2_t = nullptr; cudaGetSymbolAddress((void**)&fc2_t, g_fc2_t);

    int MB = B / 32;   // 64 batch tiles

    tr_all<<<384, 256>>>(w_qs, w_vs, fc_w, fc1_w, fc2_w);

    // G1: q = src @ w_qs^T
    sgemm<256,0,0><<<dim3(4,  MB), 256>>>(src, nullptr, 256, wqs_t, gq, 256, nullptr, nullptr);
    // G2: qW[h] = (q_h @ W_k,h) * 0.125   (K=64 per head, w_ks raw is k-major)
    sgemm<64, 1,1><<<dim3(16, MB), 256>>>(gq, nullptr, 256, (const float*)w_ks, gqW, 1024, nullptr, nullptr);
    // K2: attention (two-pass)
    k2_attn<<<B, 256>>>(seq, mask, B, attn_out);
    // G3: o = ctx_head @ w_vs^T
    sgemm<256,2,0><<<dim3(4,  MB), 256>>>(gcx, nullptr, 1024, wvs_t, go, 256, nullptr, nullptr);
    // G4: x = o @ fc_w^T + fc_b + src
    sgemm<256,0,2><<<dim3(4,  MB), 256>>>(go, nullptr, 256, fcw_t, gx, 256, fc_b, src);
    // LN in place
    ln_k<<<B/8, 256>>>(gx, ln_g, ln_b);
    // G5: h1 = relu([x, src] @ fc1^T + fc1_b)   (K=512, A switches at 256)
    sgemm<512,3,3><<<dim3(4,  MB), 256>>>(gx, src, 256, fc1_t, gh1, 256, fc1_b, nullptr);
    // G6: z = h1 @ fc2^T + fc2_b
    sgemm<256,0,4><<<dim3(4,  MB), 256>>>(gh1, nullptr, 256, fc2_t, z, 256, fc2_b, nullptr);
}

// round 13
// speedup vs baseline: 2.7618x; 1.1320x over previous
#include <cuda_runtime.h>
#include <cstdint>

#define MAXB 2048

__device__ float g_qW[MAXB * 1024];   // (q_h @ W_k,h)/TEMP  [b][h][j]
__device__ float g_ctx[MAXB * 1024];  // attn @ seq          [b][h][j]
__device__ float g_q  [MAXB * 256];
__device__ float g_o  [MAXB * 256];
__device__ float g_x  [MAXB * 256];
__device__ float g_h1 [MAXB * 256];
// transposed weights Wt[k][c] (c contiguous, 256 cols)
__device__ float g_wqs_t[256*256];
__device__ float g_wvs_t[256*256];
__device__ float g_fcw_t[256*256];
__device__ float g_fc2_t[256*256];
__device__ float g_fc1_t[512*256];

// ---------------- helpers ----------------
__device__ __forceinline__ uint64_t pk(float x, float y){
    uint64_t r; asm("mov.b64 %0, {%1,%2};" : "=l"(r) : "f"(x), "f"(y)); return r;
}
__device__ __forceinline__ float lo32(uint64_t v){ return __uint_as_float((unsigned)(v & 0xffffffffu)); }
__device__ __forceinline__ float hi32(uint64_t v){ return __uint_as_float((unsigned)(v >> 32)); }
__device__ __forceinline__ void fma2(uint64_t& d, uint64_t a, uint64_t b){
    asm("fma.rn.f32x2 %0, %1, %2, %0;" : "+l"(d) : "l"(a), "l"(b));
}
__device__ __forceinline__ void cp16(float* dst, const float* src){
    uint32_t s = (uint32_t)__cvta_generic_to_shared(dst);
    asm volatile("cp.async.cg.shared.global [%0], [%1], 16;" :: "r"(s), "l"(src));
}
#define CP_COMMIT() asm volatile("cp.async.commit_group;" ::: "memory")
#define CP_WAIT(N)  asm volatile("cp.async.wait_group %0;" :: "n"(N) : "memory")

// ---------------------------------------------------------------------------
// Weight transpose: Wt[k][c] = W[c][k].  32x32 smem tiles. (verified)
// ---------------------------------------------------------------------------
__global__ void __launch_bounds__(256) tr_all(const float* __restrict__ w_qs,
                                              const float* __restrict__ w_vs,
                                              const float* __restrict__ fc_w,
                                              const float* __restrict__ fc1_w,
                                              const float* __restrict__ fc2_w)
{
    __shared__ float ts[32][33];
    int id = blockIdx.x;
    const float* src; float* dst; int K, tile;
    if      (id < 64) { src = w_qs;  dst = g_wqs_t; K = 256; tile = id; }
    else if (id < 128){ src = w_vs;  dst = g_wvs_t; K = 256; tile = id - 64; }
    else if (id < 192){ src = fc_w;  dst = g_fcw_t; K = 256; tile = id - 128; }
    else if (id < 320){ src = fc1_w; dst = g_fc1_t; K = 512; tile = id - 192; }
    else              { src = fc2_w; dst = g_fc2_t; K = 256; tile = id - 320; }
    int ntk = K >> 5;
    int tc = tile / ntk, tk = tile % ntk;
    int c0 = tc*32, k0 = tk*32;
    int tx = threadIdx.x & 31, ty = threadIdx.x >> 5;
    #pragma unroll
    for (int r = 0; r < 32; r += 8)
        ts[ty + r][tx] = src[(size_t)(c0 + ty + r)*K + k0 + tx];
    __syncthreads();
    #pragma unroll
    for (int r = 0; r < 32; r += 8)
        dst[(size_t)(k0 + ty + r)*256 + c0 + tx] = ts[tx][ty + r];
}

// ---------------------------------------------------------------------------
// Tiled SGEMM: C[M,*] = epi( A[M,K] @ Bt[K,*] ), Bt k-major c-contiguous.
// CTA tile 32m x 64c, thread tile 2m x 4c, K-slab 32 (half the barriers of
// R11), cp.async double buffered.
// ---------------------------------------------------------------------------
template<int KTOT, int AMODE, int EPI>
__global__ void __launch_bounds__(256) sgemm(
    const float* __restrict__ A, const float* __restrict__ A2, int lda,
    const float* __restrict__ Bt, float* __restrict__ C, int ldc,
    const float* __restrict__ bias, const float* __restrict__ resid)
{
    __shared__ float As[2][32][36];
    __shared__ float Bs[2][32][64];
    int t  = threadIdx.x;
    int ct = blockIdx.x, bt = blockIdx.y;
    int bm0 = bt * 32;
    int tx = t & 15, ty = t >> 4;
    int m0 = ty * 2;

    const float* Ab; const float* Bb; int bcoff;
    if (AMODE == 1){ Ab = A + (ct>>2)*64;  Bb = Bt + (size_t)(ct>>2)*64*256; bcoff = (ct&3)*64; }
    else if (AMODE == 2){ Ab = A + ct*256; Bb = Bt; bcoff = ct*64; }
    else { Ab = A; Bb = Bt; bcoff = ct*64; }

    auto issue = [&](int j){
        int k0 = j * 32;
        const float* Ap = Ab; int k0a = k0;
        if (AMODE == 3 && k0 >= 256){ Ap = A2; k0a = k0 - 256; }
        {
            int m = t >> 3, kc = t & 7;
            cp16(&As[j&1][m][kc*4], Ap + (size_t)(bm0+m)*lda + k0a + kc*4);
        }
        #pragma unroll
        for (int p = 0; p < 2; p++){
            int u = p*256 + t;
            int kb = u >> 4, cu = u & 15;
            cp16(&Bs[j&1][kb][cu*4], Bb + (size_t)(k0+kb)*256 + bcoff + cu*4);
        }
        CP_COMMIT();
    };

    uint64_t a01[2] = {0,0}, a23[2] = {0,0};
    constexpr int NS = KTOT / 32;
    issue(0);
    if (NS > 1) issue(1);
    for (int j = 0; j < NS; j++){
        if (j < NS-1) CP_WAIT(1); else CP_WAIT(0);
        __syncthreads();
        int buf = j & 1;
        #pragma unroll
        for (int kk = 0; kk < 32; kk++){
            ulonglong2 b4 = *(const ulonglong2*)(&Bs[buf][kk][tx*4]);
            float x0 = As[buf][m0][kk];
            float x1 = As[buf][m0+1][kk];
            uint64_t d0 = pk(x0, x0), d1 = pk(x1, x1);
            fma2(a01[0], b4.x, d0); fma2(a23[0], b4.y, d0);
            fma2(a01[1], b4.x, d1); fma2(a23[1], b4.y, d1);
        }
        __syncthreads();
        if (j + 2 < NS) issue(j + 2);
    }

    int cg = ct*64 + tx*4;
    #pragma unroll
    for (int i = 0; i < 2; i++){
        int mg = bm0 + m0 + i;
        float4 v = make_float4(lo32(a01[i]), hi32(a01[i]),
                               lo32(a23[i]), hi32(a23[i]));
        if (EPI == 1){ v.x *= 0.125f; v.y *= 0.125f; v.z *= 0.125f; v.w *= 0.125f; }
        if (EPI >= 2){
            float4 bb = *(const float4*)(bias + cg);
            v.x += bb.x; v.y += bb.y; v.z += bb.z; v.w += bb.w;
        }
        if (EPI == 2){
            float4 rr = *(const float4*)(resid + (size_t)mg*256 + cg);
            v.x += rr.x; v.y += rr.y; v.z += rr.z; v.w += rr.w;
        }
        if (EPI == 3){
            v.x = fmaxf(v.x, 0.f); v.y = fmaxf(v.y, 0.f);
            v.z = fmaxf(v.z, 0.f); v.w = fmaxf(v.w, 0.f);
        }
        *(float4*)(C + (size_t)mg*ldc + cg) = v;
    }
}

// ---------------------------------------------------------------------------
// LayerNorm in-place on x[B,256]; one warp per row. (verified)
// ---------------------------------------------------------------------------
__global__ void __launch_bounds__(256) ln_k(float* __restrict__ x,
                                            const float* __restrict__ ln_g,
                                            const float* __restrict__ ln_b)
{
    int w = threadIdx.x >> 5, lane = threadIdx.x & 31;
    int r = blockIdx.x*8 + w;
    float* xr = x + (size_t)r*256 + lane*8;
    float4 v0 = *(const float4*)xr;
    float4 v1 = *(const float4*)(xr + 4);
    float s  = v0.x+v0.y+v0.z+v0.w + v1.x+v1.y+v1.z+v1.w;
    float s2 = v0.x*v0.x+v0.y*v0.y+v0.z*v0.z+v0.w*v0.w
             + v1.x*v1.x+v1.y*v1.y+v1.z*v1.z+v1.w*v1.w;
    #pragma unroll
    for (int o = 16; o > 0; o >>= 1){
        s  += __shfl_xor_sync(0xffffffffu, s,  o);
        s2 += __shfl_xor_sync(0xffffffffu, s2, o);
    }
    float mu = s * (1.f/256.f);
    float rs = rsqrtf(s2 * (1.f/256.f) - mu*mu + 1e-5f);
    float4 g0 = *(const float4*)(ln_g + lane*8);
    float4 g1 = *(const float4*)(ln_g + lane*8 + 4);
    float4 b0 = *(const float4*)(ln_b + lane*8);
    float4 b1 = *(const float4*)(ln_b + lane*8 + 4);
    v0.x = (v0.x-mu)*rs*g0.x + b0.x; v0.y = (v0.y-mu)*rs*g0.y + b0.y;
    v0.z = (v0.z-mu)*rs*g0.z + b0.z; v0.w = (v0.w-mu)*rs*g0.w + b0.w;
    v1.x = (v1.x-mu)*rs*g1.x + b1.x; v1.y = (v1.y-mu)*rs*g1.y + b1.y;
    v1.z = (v1.z-mu)*rs*g1.z + b1.z; v1.w = (v1.w-mu)*rs*g1.w + b1.w;
    *(float4*)xr = v0;
    *(float4*)(xr + 4) = v1;
}

// ---------------------------------------------------------------------------
// K2 v3: two-pass attention. Pass 1 unroll-4 (8 LDG.128 in flight/warp),
// 6-SHFL multi-head reduce, one softmax, pass 2 with 4-way split accumulators
// from L1-hot seq.
// ---------------------------------------------------------------------------
__global__ void __launch_bounds__(256, 3) k2_attn(const float* __restrict__ seq,
                                                  const void* __restrict__ mask,
                                                  int B,
                                                  float* __restrict__ attn_out)
{
    __shared__ __align__(16) float sc_s[512];   // [h][n]
    __shared__ __align__(16) float e_s[512];    // [n][h]
    __shared__ __align__(16) float msk_s[512];  // [h][n] 1=masked
    __shared__ int s_u8;

    int t = threadIdx.x, b = blockIdx.x;
    int w = t >> 5, lane = t & 31;

    if (t == 0) s_u8 = 0;
    __syncthreads();
    { unsigned wv = ((const unsigned*)mask)[t]; if (wv > 1u) atomicOr(&s_u8, 1); }
    __syncthreads();
    int is_u8 = s_u8;

    // stage mask flags (mask row (4b+h)%B — reference head-major tiling quirk)
    #pragma unroll
    for (int p = 0; p < 2; p++){
        int idx = p*256 + t;
        int h = idx >> 7, n = idx & 127;
        int mrow = (4*b + h) % B;
        int mv = is_u8 ? (int)((const unsigned char*)mask)[(size_t)mrow*128 + n]
                       : ((const int*)mask)[(size_t)mrow*128 + n];
        msk_s[idx] = mv ? 1.f : 0.f;
    }

    // qW in registers: q[h][0..3] u64 = 8 floats at lane*8
    uint64_t q[4][4];
    {
        const ulonglong2* qp = (const ulonglong2*)(g_qW + (size_t)b*1024 + lane*8);
        #pragma unroll
        for (int h = 0; h < 4; h++){
            ulonglong2 v0 = qp[h*64];
            ulonglong2 v1 = qp[h*64 + 1];
            q[h][0] = v0.x; q[h][1] = v0.y; q[h][2] = v1.x; q[h][3] = v1.y;
        }
    }
    const float* gseq = seq + (size_t)b*32768;
    __syncthreads();   // msk_s ready

    // ---- pass 1: scores, rows n = r*8 + w, 4 rows in flight ----
    #pragma unroll 4
    for (int r = 0; r < 16; r++){
        int n = r*8 + w;
        const float4* vp = (const float4*)(gseq + n*256 + lane*8);
        float4 va = __ldg(vp), vb = __ldg(vp + 1);
        uint64_t u0 = pk(va.x, va.y), u1 = pk(va.z, va.w);
        uint64_t u2 = pk(vb.x, vb.y), u3 = pk(vb.z, vb.w);
        float sc4[4];
        #pragma unroll
        for (int h = 0; h < 4; h++){
            uint64_t a = 0;
            fma2(a, u0, q[h][0]); fma2(a, u1, q[h][1]);
            fma2(a, u2, q[h][2]); fma2(a, u3, q[h][3]);
            sc4[h] = lo32(a) + hi32(a);
        }
        // 6-SHFL 4-head reduce: lane ends with head (lane&3)'s full sum
        bool b0 = (lane & 1) != 0;
        float k01 = b0 ? sc4[1] : sc4[0];
        float s01 = b0 ? sc4[0] : sc4[1];
        float m01 = k01 + __shfl_xor_sync(0xffffffffu, s01, 1);
        float k23 = b0 ? sc4[3] : sc4[2];
        float s23 = b0 ? sc4[2] : sc4[3];
        float m23 = k23 + __shfl_xor_sync(0xffffffffu, s23, 1);
        bool b1 = (lane & 2) != 0;
        float kk = b1 ? m23 : m01;
        float ss = b1 ? m01 : m23;
        float sv = kk + __shfl_xor_sync(0xffffffffu, ss, 2);
        sv += __shfl_xor_sync(0xffffffffu, sv, 4);
        sv += __shfl_xor_sync(0xffffffffu, sv, 8);
        sv += __shfl_xor_sync(0xffffffffu, sv, 16);
        if (lane < 4){
            int h = lane;
            float f = msk_s[h*128 + n];
            sc_s[h*128 + n] = (f > 0.5f) ? -1e10f : sv;
        }
    }
    __syncthreads();

    // ---- one softmax: warp h < 4 handles head h ----
    if (w < 4){
        int h = w;
        float v0 = sc_s[h*128 + lane];
        float v1 = sc_s[h*128 + lane + 32];
        float v2 = sc_s[h*128 + lane + 64];
        float v3 = sc_s[h*128 + lane + 96];
        float m = fmaxf(fmaxf(v0, v1), fmaxf(v2, v3));
        #pragma unroll
        for (int o = 16; o > 0; o >>= 1) m = fmaxf(m, __shfl_xor_sync(0xffffffffu, m, o));
        float e0 = expf(v0 - m), e1 = expf(v1 - m), e2 = expf(v2 - m), e3 = expf(v3 - m);
        float s = e0 + e1 + e2 + e3;
        #pragma unroll
        for (int o = 16; o > 0; o >>= 1) s += __shfl_xor_sync(0xffffffffu, s, o);
        float inv = 1.f / s;
        e0 *= inv; e1 *= inv; e2 *= inv; e3 *= inv;
        e_s[lane*4 + h]       = e0;
        e_s[(lane+32)*4 + h]  = e1;
        e_s[(lane+64)*4 + h]  = e2;
        e_s[(lane+96)*4 + h]  = e3;
        if (attn_out){
            float* ao = attn_out + (size_t)b*512 + h*128;
            ao[lane] = e0; ao[lane+32] = e1; ao[lane+64] = e2; ao[lane+96] = e3;
        }
    }
    __syncthreads();

    // ---- pass 2: ctx[h][t] = sum_n attn[h][n]*seq[n][t], 4 split chains ----
    uint64_t c0a = 0, c0b = 0, c1a = 0, c1b = 0;
    const float* sp = gseq + t;
    #pragma unroll 8
    for (int n = 0; n < 128; n += 2){
        float sv0 = __ldg(sp + n*256);
        float sv1 = __ldg(sp + (n+1)*256);
        uint64_t s0 = pk(sv0, sv0), s1 = pk(sv1, sv1);
        ulonglong2 ea = *(const ulonglong2*)(e_s + n*4);
        ulonglong2 eb = *(const ulonglong2*)(e_s + n*4 + 4);
        fma2(c0a, s0, ea.x); fma2(c1a, s0, ea.y);
        fma2(c0b, s1, eb.x); fma2(c1b, s1, eb.y);
    }
    float* cbg = g_ctx + (size_t)b*1024;
    cbg[t]       = lo32(c0a) + lo32(c0b);
    cbg[256 + t] = hi32(c0a) + hi32(c0b);
    cbg[512 + t] = lo32(c1a) + lo32(c1b);
    cbg[768 + t] = hi32(c1a) + hi32(c1b);
}

// ---------------------------------------------------------------------------
extern "C" void kernel_launch(void* const* d_in, const int* in_sizes, int n_in,
                              void* d_out, int out_size)
{
    const float* src   = (const float*)d_in[0];
    const float* seq   = (const float*)d_in[1];
    const void*  mask  = d_in[2];
    const float* w_qs  = (const float*)d_in[3];
    const float* w_ks  = (const float*)d_in[4];
    const float* w_vs  = (const float*)d_in[5];
    const float* fc_w  = (const float*)d_in[6];
    const float* fc_b  = (const float*)d_in[7];
    const float* ln_g  = (const float*)d_in[8];
    const float* ln_b  = (const float*)d_in[9];
    const float* fc1_w = (const float*)d_in[10];
    const float* fc1_b = (const float*)d_in[11];
    const float* fc2_w = (const float*)d_in[12];
    const float* fc2_b = (const float*)d_in[13];

    int B = in_sizes[0] / 256;
    if (B > MAXB) B = MAXB;

    float* z = (float*)d_out;
    float* attn_out = nullptr;
    if (out_size >= B*256 + B*512) attn_out = z + (size_t)B*256;

    float* gq  = nullptr; cudaGetSymbolAddress((void**)&gq,  g_q);
    float* gqW = nullptr; cudaGetSymbolAddress((void**)&gqW, g_qW);
    float* gcx = nullptr; cudaGetSymbolAddress((void**)&gcx, g_ctx);
    float* go  = nullptr; cudaGetSymbolAddress((void**)&go,  g_o);
    float* gx  = nullptr; cudaGetSymbolAddress((void**)&gx,  g_x);
    float* gh1 = nullptr; cudaGetSymbolAddress((void**)&gh1, g_h1);
    float* wqs_t = nullptr; cudaGetSymbolAddress((void**)&wqs_t, g_wqs_t);
    float* wvs_t = nullptr; cudaGetSymbolAddress((void**)&wvs_t, g_wvs_t);
    float* fcw_t = nullptr; cudaGetSymbolAddress((void**)&fcw_t, g_fcw_t);
    float* fc1_t = nullptr; cudaGetSymbolAddress((void**)&fc1_t, g_fc1_t);
    float* fc2_t = nullptr; cudaGetSymbolAddress((void**)&fc2_t, g_fc2_t);

    int MB = B / 32;   // 64 batch tiles

    tr_all<<<384, 256>>>(w_qs, w_vs, fc_w, fc1_w, fc2_w);

    // G1: q = src @ w_qs^T
    sgemm<256,0,0><<<dim3(4,  MB), 256>>>(src, nullptr, 256, wqs_t, gq, 256, nullptr, nullptr);
    // G2: qW[h] = (q_h @ W_k,h) * 0.125   (K=64 per head, w_ks raw is k-major)
    sgemm<64, 1,1><<<dim3(16, MB), 256>>>(gq, nullptr, 256, (const float*)w_ks, gqW, 1024, nullptr, nullptr);
    // K2: attention (two-pass)
    k2_attn<<<B, 256>>>(seq, mask, B, attn_out);
    // G3: o = ctx_head @ w_vs^T
    sgemm<256,2,0><<<dim3(4,  MB), 256>>>(gcx, nullptr, 1024, wvs_t, go, 256, nullptr, nullptr);
    // G4: x = o @ fc_w^T + fc_b + src
    sgemm<256,0,2><<<dim3(4,  MB), 256>>>(go, nullptr, 256, fcw_t, gx, 256, fc_b, src);
    // LN in place
    ln_k<<<B/8, 256>>>(gx, ln_g, ln_b);
    // G5: h1 = relu([x, src] @ fc1^T + fc1_b)   (K=512, A switches at 256)
    sgemm<512,3,3><<<dim3(4,  MB), 256>>>(gx, src, 256, fc1_t, gh1, 256, fc1_b, nullptr);
    // G6: z = h1 @ fc2^T + fc2_b
    sgemm<256,0,4><<<dim3(4,  MB), 256>>>(gh1, nullptr, 256, fc2_t, z, 256, fc2_b, nullptr);
}

// round 14
// speedup vs baseline: 3.1118x; 1.1267x over previous
#include <cuda_runtime.h>
#include <cstdint>

#define MAXB 2048

__device__ float g_qW[MAXB * 1024];   // (q_h @ W_k,h)/TEMP  [b][h][j]
__device__ float g_ctx[MAXB * 1024];  // attn @ seq          [b][h][j]
__device__ float g_q  [MAXB * 256];
__device__ float g_o  [MAXB * 256];
__device__ float g_x  [MAXB * 256];
__device__ float g_h1 [MAXB * 256];
// transposed weights Wt[k][c] (c contiguous, 256 cols)
__device__ float g_wqs_t[256*256];
__device__ float g_wvs_t[256*256];
__device__ float g_fcw_t[256*256];
__device__ float g_fc2_t[256*256];
__device__ float g_fc1_t[512*256];

// ---------------- helpers ----------------
__device__ __forceinline__ uint64_t pk(float x, float y){
    uint64_t r; asm("mov.b64 %0, {%1,%2};" : "=l"(r) : "f"(x), "f"(y)); return r;
}
__device__ __forceinline__ float lo32(uint64_t v){ return __uint_as_float((unsigned)(v & 0xffffffffu)); }
__device__ __forceinline__ float hi32(uint64_t v){ return __uint_as_float((unsigned)(v >> 32)); }
__device__ __forceinline__ void fma2(uint64_t& d, uint64_t a, uint64_t b){
    asm("fma.rn.f32x2 %0, %1, %2, %0;" : "+l"(d) : "l"(a), "l"(b));
}
__device__ __forceinline__ void cp16(float* dst, const float* src){
    uint32_t s = (uint32_t)__cvta_generic_to_shared(dst);
    asm volatile("cp.async.cg.shared.global [%0], [%1], 16;" :: "r"(s), "l"(src));
}
#define CP_COMMIT() asm volatile("cp.async.commit_group;" ::: "memory")
#define CP_WAIT(N)  asm volatile("cp.async.wait_group %0;" :: "n"(N) : "memory")

// ---------------------------------------------------------------------------
// Weight transpose: Wt[k][c] = W[c][k].  32x32 smem tiles. (verified)
// ---------------------------------------------------------------------------
__global__ void __launch_bounds__(256) tr_all(const float* __restrict__ w_qs,
                                              const float* __restrict__ w_vs,
                                              const float* __restrict__ fc_w,
                                              const float* __restrict__ fc1_w,
                                              const float* __restrict__ fc2_w)
{
    __shared__ float ts[32][33];
    int id = blockIdx.x;
    const float* src; float* dst; int K, tile;
    if      (id < 64) { src = w_qs;  dst = g_wqs_t; K = 256; tile = id; }
    else if (id < 128){ src = w_vs;  dst = g_wvs_t; K = 256; tile = id - 64; }
    else if (id < 192){ src = fc_w;  dst = g_fcw_t; K = 256; tile = id - 128; }
    else if (id < 320){ src = fc1_w; dst = g_fc1_t; K = 512; tile = id - 192; }
    else              { src = fc2_w; dst = g_fc2_t; K = 256; tile = id - 320; }
    int ntk = K >> 5;
    int tc = tile / ntk, tk = tile % ntk;
    int c0 = tc*32, k0 = tk*32;
    int tx = threadIdx.x & 31, ty = threadIdx.x >> 5;
    #pragma unroll
    for (int r = 0; r < 32; r += 8)
        ts[ty + r][tx] = src[(size_t)(c0 + ty + r)*K + k0 + tx];
    __syncthreads();
    #pragma unroll
    for (int r = 0; r < 32; r += 8)
        dst[(size_t)(k0 + ty + r)*256 + c0 + tx] = ts[tx][ty + r];
}

// ---------------------------------------------------------------------------
// Tiled SGEMM v2: C[M,*] = epi( A[M,K] @ Bt[K,*] ), Bt k-major c-contiguous.
// CTA tile 64m x 64c (ONE WAVE: grid 4x32 = 128 CTAs for 256-col outputs),
// thread tile 4m x 4c, K-slab 32, cp.async double buffered.
// ---------------------------------------------------------------------------
template<int KTOT, int AMODE, int EPI>
__global__ void __launch_bounds__(256) sgemm(
    const float* __restrict__ A, const float* __restrict__ A2, int lda,
    const float* __restrict__ Bt, float* __restrict__ C, int ldc,
    const float* __restrict__ bias, const float* __restrict__ resid)
{
    __shared__ float As[2][64][36];
    __shared__ float Bs[2][32][64];
    int t  = threadIdx.x;
    int ct = blockIdx.x, bt = blockIdx.y;
    int bm0 = bt * 64;
    int tx = t & 15, ty = t >> 4;
    int m0 = ty * 4;

    const float* Ab; const float* Bb; int bcoff;
    if (AMODE == 1){ Ab = A + (ct>>2)*64;  Bb = Bt + (size_t)(ct>>2)*64*256; bcoff = (ct&3)*64; }
    else if (AMODE == 2){ Ab = A + ct*256; Bb = Bt; bcoff = ct*64; }
    else { Ab = A; Bb = Bt; bcoff = ct*64; }

    auto issue = [&](int j){
        int k0 = j * 32;
        const float* Ap = Ab; int k0a = k0;
        if (AMODE == 3 && k0 >= 256){ Ap = A2; k0a = k0 - 256; }
        #pragma unroll
        for (int p = 0; p < 2; p++){
            int u = p*256 + t;
            int m = u >> 3, kc = u & 7;
            cp16(&As[j&1][m][kc*4], Ap + (size_t)(bm0+m)*lda + k0a + kc*4);
        }
        #pragma unroll
        for (int p = 0; p < 2; p++){
            int u = p*256 + t;
            int kb = u >> 4, cu = u & 15;
            cp16(&Bs[j&1][kb][cu*4], Bb + (size_t)(k0+kb)*256 + bcoff + cu*4);
        }
        CP_COMMIT();
    };

    uint64_t a01[4] = {0,0,0,0}, a23[4] = {0,0,0,0};
    constexpr int NS = KTOT / 32;
    issue(0);
    if (NS > 1) issue(1);
    for (int j = 0; j < NS; j++){
        if (j < NS-1) CP_WAIT(1); else CP_WAIT(0);
        __syncthreads();
        int buf = j & 1;
        #pragma unroll
        for (int kk = 0; kk < 32; kk++){
            ulonglong2 b4 = *(const ulonglong2*)(&Bs[buf][kk][tx*4]);
            #pragma unroll
            for (int i = 0; i < 4; i++){
                float x = As[buf][m0+i][kk];
                uint64_t d = pk(x, x);
                fma2(a01[i], b4.x, d);
                fma2(a23[i], b4.y, d);
            }
        }
        __syncthreads();
        if (j + 2 < NS) issue(j + 2);
    }

    int cg = ct*64 + tx*4;
    #pragma unroll
    for (int i = 0; i < 4; i++){
        int mg = bm0 + m0 + i;
        float4 v = make_float4(lo32(a01[i]), hi32(a01[i]),
                               lo32(a23[i]), hi32(a23[i]));
        if (EPI == 1){ v.x *= 0.125f; v.y *= 0.125f; v.z *= 0.125f; v.w *= 0.125f; }
        if (EPI >= 2){
            float4 bb = *(const float4*)(bias + cg);
            v.x += bb.x; v.y += bb.y; v.z += bb.z; v.w += bb.w;
        }
        if (EPI == 2){
            float4 rr = *(const float4*)(resid + (size_t)mg*256 + cg);
            v.x += rr.x; v.y += rr.y; v.z += rr.z; v.w += rr.w;
        }
        if (EPI == 3){
            v.x = fmaxf(v.x, 0.f); v.y = fmaxf(v.y, 0.f);
            v.z = fmaxf(v.z, 0.f); v.w = fmaxf(v.w, 0.f);
        }
        *(float4*)(C + (size_t)mg*ldc + cg) = v;
    }
}

// ---------------------------------------------------------------------------
// LayerNorm in-place on x[B,256]; one warp per row. (verified)
// ---------------------------------------------------------------------------
__global__ void __launch_bounds__(256) ln_k(float* __restrict__ x,
                                            const float* __restrict__ ln_g,
                                            const float* __restrict__ ln_b)
{
    int w = threadIdx.x >> 5, lane = threadIdx.x & 31;
    int r = blockIdx.x*8 + w;
    float* xr = x + (size_t)r*256 + lane*8;
    float4 v0 = *(const float4*)xr;
    float4 v1 = *(const float4*)(xr + 4);
    float s  = v0.x+v0.y+v0.z+v0.w + v1.x+v1.y+v1.z+v1.w;
    float s2 = v0.x*v0.x+v0.y*v0.y+v0.z*v0.z+v0.w*v0.w
             + v1.x*v1.x+v1.y*v1.y+v1.z*v1.z+v1.w*v1.w;
    #pragma unroll
    for (int o = 16; o > 0; o >>= 1){
        s  += __shfl_xor_sync(0xffffffffu, s,  o);
        s2 += __shfl_xor_sync(0xffffffffu, s2, o);
    }
    float mu = s * (1.f/256.f);
    float rs = rsqrtf(s2 * (1.f/256.f) - mu*mu + 1e-5f);
    float4 g0 = *(const float4*)(ln_g + lane*8);
    float4 g1 = *(const float4*)(ln_g + lane*8 + 4);
    float4 b0 = *(const float4*)(ln_b + lane*8);
    float4 b1 = *(const float4*)(ln_b + lane*8 + 4);
    v0.x = (v0.x-mu)*rs*g0.x + b0.x; v0.y = (v0.y-mu)*rs*g0.y + b0.y;
    v0.z = (v0.z-mu)*rs*g0.z + b0.z; v0.w = (v0.w-mu)*rs*g0.w + b0.w;
    v1.x = (v1.x-mu)*rs*g1.x + b1.x; v1.y = (v1.y-mu)*rs*g1.y + b1.y;
    v1.z = (v1.z-mu)*rs*g1.z + b1.z; v1.w = (v1.w-mu)*rs*g1.w + b1.w;
    *(float4*)xr = v0;
    *(float4*)(xr + 4) = v1;
}

// ---------------------------------------------------------------------------
// K2 v3: two-pass attention (verified R13). Pass 1 unroll-4, 6-SHFL reduce,
// one softmax, pass 2 with 4 split accumulator chains from L1-hot seq.
// ---------------------------------------------------------------------------
__global__ void __launch_bounds__(256, 3) k2_attn(const float* __restrict__ seq,
                                                  const void* __restrict__ mask,
                                                  int B,
                                                  float* __restrict__ attn_out)
{
    __shared__ __align__(16) float sc_s[512];   // [h][n]
    __shared__ __align__(16) float e_s[512];    // [n][h]
    __shared__ __align__(16) float msk_s[512];  // [h][n] 1=masked
    __shared__ int s_u8;

    int t = threadIdx.x, b = blockIdx.x;
    int w = t >> 5, lane = t & 31;

    if (t == 0) s_u8 = 0;
    __syncthreads();
    { unsigned wv = ((const unsigned*)mask)[t]; if (wv > 1u) atomicOr(&s_u8, 1); }
    __syncthreads();
    int is_u8 = s_u8;

    #pragma unroll
    for (int p = 0; p < 2; p++){
        int idx = p*256 + t;
        int h = idx >> 7, n = idx & 127;
        int mrow = (4*b + h) % B;
        int mv = is_u8 ? (int)((const unsigned char*)mask)[(size_t)mrow*128 + n]
                       : ((const int*)mask)[(size_t)mrow*128 + n];
        msk_s[idx] = mv ? 1.f : 0.f;
    }

    uint64_t q[4][4];
    {
        const ulonglong2* qp = (const ulonglong2*)(g_qW + (size_t)b*1024 + lane*8);
        #pragma unroll
        for (int h = 0; h < 4; h++){
            ulonglong2 v0 = qp[h*64];
            ulonglong2 v1 = qp[h*64 + 1];
            q[h][0] = v0.x; q[h][1] = v0.y; q[h][2] = v1.x; q[h][3] = v1.y;
        }
    }
    const float* gseq = seq + (size_t)b*32768;
    __syncthreads();

    #pragma unroll 4
    for (int r = 0; r < 16; r++){
        int n = r*8 + w;
        const float4* vp = (const float4*)(gseq + n*256 + lane*8);
        float4 va = __ldg(vp), vb = __ldg(vp + 1);
        uint64_t u0 = pk(va.x, va.y), u1 = pk(va.z, va.w);
        uint64_t u2 = pk(vb.x, vb.y), u3 = pk(vb.z, vb.w);
        float sc4[4];
        #pragma unroll
        for (int h = 0; h < 4; h++){
            uint64_t a = 0;
            fma2(a, u0, q[h][0]); fma2(a, u1, q[h][1]);
            fma2(a, u2, q[h][2]); fma2(a, u3, q[h][3]);
            sc4[h] = lo32(a) + hi32(a);
        }
        bool b0 = (lane & 1) != 0;
        float k01 = b0 ? sc4[1] : sc4[0];
        float s01 = b0 ? sc4[0] : sc4[1];
        float m01 = k01 + __shfl_xor_sync(0xffffffffu, s01, 1);
        float k23 = b0 ? sc4[3] : sc4[2];
        float s23 = b0 ? sc4[2] : sc4[3];
        float m23 = k23 + __shfl_xor_sync(0xffffffffu, s23, 1);
        bool b1 = (lane & 2) != 0;
        float kk = b1 ? m23 : m01;
        float ss = b1 ? m01 : m23;
        float sv = kk + __shfl_xor_sync(0xffffffffu, ss, 2);
        sv += __shfl_xor_sync(0xffffffffu, sv, 4);
        sv += __shfl_xor_sync(0xffffffffu, sv, 8);
        sv += __shfl_xor_sync(0xffffffffu, sv, 16);
        if (lane < 4){
            int h = lane;
            float f = msk_s[h*128 + n];
            sc_s[h*128 + n] = (f > 0.5f) ? -1e10f : sv;
        }
    }
    __syncthreads();

    if (w < 4){
        int h = w;
        float v0 = sc_s[h*128 + lane];
        float v1 = sc_s[h*128 + lane + 32];
        float v2 = sc_s[h*128 + lane + 64];
        float v3 = sc_s[h*128 + lane + 96];
        float m = fmaxf(fmaxf(v0, v1), fmaxf(v2, v3));
        #pragma unroll
        for (int o = 16; o > 0; o >>= 1) m = fmaxf(m, __shfl_xor_sync(0xffffffffu, m, o));
        float e0 = expf(v0 - m), e1 = expf(v1 - m), e2 = expf(v2 - m), e3 = expf(v3 - m);
        float s = e0 + e1 + e2 + e3;
        #pragma unroll
        for (int o = 16; o > 0; o >>= 1) s += __shfl_xor_sync(0xffffffffu, s, o);
        float inv = 1.f / s;
        e0 *= inv; e1 *= inv; e2 *= inv; e3 *= inv;
        e_s[lane*4 + h]       = e0;
        e_s[(lane+32)*4 + h]  = e1;
        e_s[(lane+64)*4 + h]  = e2;
        e_s[(lane+96)*4 + h]  = e3;
        if (attn_out){
            float* ao = attn_out + (size_t)b*512 + h*128;
            ao[lane] = e0; ao[lane+32] = e1; ao[lane+64] = e2; ao[lane+96] = e3;
        }
    }
    __syncthreads();

    uint64_t c0a = 0, c0b = 0, c1a = 0, c1b = 0;
    const float* sp = gseq + t;
    #pragma unroll 8
    for (int n = 0; n < 128; n += 2){
        float sv0 = __ldg(sp + n*256);
        float sv1 = __ldg(sp + (n+1)*256);
        uint64_t s0 = pk(sv0, sv0), s1 = pk(sv1, sv1);
        ulonglong2 ea = *(const ulonglong2*)(e_s + n*4);
        ulonglong2 eb = *(const ulonglong2*)(e_s + n*4 + 4);
        fma2(c0a, s0, ea.x); fma2(c1a, s0, ea.y);
        fma2(c0b, s1, eb.x); fma2(c1b, s1, eb.y);
    }
    float* cbg = g_ctx + (size_t)b*1024;
    cbg[t]       = lo32(c0a) + lo32(c0b);
    cbg[256 + t] = hi32(c0a) + hi32(c0b);
    cbg[512 + t] = lo32(c1a) + lo32(c1b);
    cbg[768 + t] = hi32(c1a) + hi32(c1b);
}

// ---------------------------------------------------------------------------
extern "C" void kernel_launch(void* const* d_in, const int* in_sizes, int n_in,
                              void* d_out, int out_size)
{
    const float* src   = (const float*)d_in[0];
    const float* seq   = (const float*)d_in[1];
    const void*  mask  = d_in[2];
    const float* w_qs  = (const float*)d_in[3];
    const float* w_ks  = (const float*)d_in[4];
    const float* w_vs  = (const float*)d_in[5];
    const float* fc_w  = (const float*)d_in[6];
    const float* fc_b  = (const float*)d_in[7];
    const float* ln_g  = (const float*)d_in[8];
    const float* ln_b  = (const float*)d_in[9];
    const float* fc1_w = (const float*)d_in[10];
    const float* fc1_b = (const float*)d_in[11];
    const float* fc2_w = (const float*)d_in[12];
    const float* fc2_b = (const float*)d_in[13];

    int B = in_sizes[0] / 256;
    if (B > MAXB) B = MAXB;

    float* z = (float*)d_out;
    float* attn_out = nullptr;
    if (out_size >= B*256 + B*512) attn_out = z + (size_t)B*256;

    float* gq  = nullptr; cudaGetSymbolAddress((void**)&gq,  g_q);
    float* gqW = nullptr; cudaGetSymbolAddress((void**)&gqW, g_qW);
    float* gcx = nullptr; cudaGetSymbolAddress((void**)&gcx, g_ctx);
    float* go  = nullptr; cudaGetSymbolAddress((void**)&go,  g_o);
    float* gx  = nullptr; cudaGetSymbolAddress((void**)&gx,  g_x);
    float* gh1 = nullptr; cudaGetSymbolAddress((void**)&gh1, g_h1);
    float* wqs_t = nullptr; cudaGetSymbolAddress((void**)&wqs_t, g_wqs_t);
    float* wvs_t = nullptr; cudaGetSymbolAddress((void**)&wvs_t, g_wvs_t);
    float* fcw_t = nullptr; cudaGetSymbolAddress((void**)&fcw_t, g_fcw_t);
    float* fc1_t = nullptr; cudaGetSymbolAddress((void**)&fc1_t, g_fc1_t);
    float* fc2_t = nullptr; cudaGetSymbolAddress((void**)&fc2_t, g_fc2_t);

    int MB = B / 64;   // 32 batch tiles (64 rows per CTA)

    tr_all<<<384, 256>>>(w_qs, w_vs, fc_w, fc1_w, fc2_w);

    // G1: q = src @ w_qs^T                       (grid 4x32 = 128 CTAs, 1 wave)
    sgemm<256,0,0><<<dim3(4,  MB), 256>>>(src, nullptr, 256, wqs_t, gq, 256, nullptr, nullptr);
    // G2: qW[h] = (q_h @ W_k,h) * 0.125
    sgemm<64, 1,1><<<dim3(16, MB), 256>>>(gq, nullptr, 256, (const float*)w_ks, gqW, 1024, nullptr, nullptr);
    // K2: attention (two-pass)
    k2_attn<<<B, 256>>>(seq, mask, B, attn_out);
    // G3: o = ctx_head @ w_vs^T
    sgemm<256,2,0><<<dim3(4,  MB), 256>>>(gcx, nullptr, 1024, wvs_t, go, 256, nullptr, nullptr);
    // G4: x = o @ fc_w^T + fc_b + src
    sgemm<256,0,2><<<dim3(4,  MB), 256>>>(go, nullptr, 256, fcw_t, gx, 256, fc_b, src);
    // LN in place
    ln_k<<<B/8, 256>>>(gx, ln_g, ln_b);
    // G5: h1 = relu([x, src] @ fc1^T + fc1_b)   (K=512, A switches at 256)
    sgemm<512,3,3><<<dim3(4,  MB), 256>>>(gx, src, 256, fc1_t, gh1, 256, fc1_b, nullptr);
    // G6: z = h1 @ fc2^T + fc2_b
    sgemm<256,0,4><<<dim3(4,  MB), 256>>>(gh1, nullptr, 256, fc2_t, z, 256, fc2_b, nullptr);
}